// round 13
// baseline (speedup 1.0000x reference)
#include <cuda_runtime.h>
#include <cuda_bf16.h>
#include <cuda_fp16.h>
#include <cstdint>
#include <math.h>

// Problem constants
constexpr int B_  = 4;
constexpr int T_  = 1024;
constexpr int C_  = 768;
constexpr int NH_ = 12;
constexpr int HD_ = 64;
constexpr int C3_ = 3 * C_;          // 2304
constexpr int MR_ = B_ * T_;         // 4096 rows

// Scratch (static device globals — no allocation)
__device__ __nv_bfloat16 g_xh[(size_t)MR_ * C_];
__device__ __nv_bfloat16 g_xl[(size_t)MR_ * C_];
__device__ __nv_bfloat16 g_wqh[(size_t)C_ * C3_];
__device__ __nv_bfloat16 g_wql[(size_t)C_ * C3_];
__device__ __nv_bfloat16 g_wph[(size_t)C_ * C_];
__device__ __nv_bfloat16 g_wpl[(size_t)C_ * C_];
__device__ __nv_bfloat16 g_ah[(size_t)MR_ * C_];           // attention out hi
__device__ __nv_bfloat16 g_al[(size_t)MR_ * C_];           // attention out lo
// f16 hi/lo splits of q,k,v (written by QKV GEMM epilogue)
__device__ __half g_fqh[(size_t)MR_ * C_];
__device__ __half g_fql[(size_t)MR_ * C_];
__device__ __half g_fkh[(size_t)MR_ * C_];
__device__ __half g_fkl[(size_t)MR_ * C_];
__device__ __half g_fvh[(size_t)MR_ * C_];
__device__ __half g_fvl[(size_t)MR_ * C_];

// ---------------------------------------------------------------------------
// helpers
// ---------------------------------------------------------------------------
__device__ __forceinline__ uint32_t smem_u32(const void* p) {
    uint32_t a;
    asm("{ .reg .u64 t; cvta.to.shared.u64 t, %1; cvt.u32.u64 %0, t; }"
        : "=r"(a) : "l"(p));
    return a;
}
__device__ __forceinline__ void cp_async16(uint32_t saddr, const void* gptr) {
    asm volatile("cp.async.cg.shared.global [%0], [%1], 16;"
                 :: "r"(saddr), "l"(gptr));
}
__device__ __forceinline__ void cp_commit() {
    asm volatile("cp.async.commit_group;");
}
template <int N>
__device__ __forceinline__ void cp_wait() {
    asm volatile("cp.async.wait_group %0;" :: "n"(N));
}
__device__ __forceinline__ void ldm_x4(uint32_t* r, uint32_t addr) {
    asm volatile("ldmatrix.sync.aligned.m8n8.x4.shared.b16 {%0,%1,%2,%3}, [%4];"
                 : "=r"(r[0]), "=r"(r[1]), "=r"(r[2]), "=r"(r[3]) : "r"(addr));
}
__device__ __forceinline__ void ldm_x4_t(uint32_t* r, uint32_t addr) {
    asm volatile("ldmatrix.sync.aligned.m8n8.x4.trans.shared.b16 {%0,%1,%2,%3}, [%4];"
                 : "=r"(r[0]), "=r"(r[1]), "=r"(r[2]), "=r"(r[3]) : "r"(addr));
}
__device__ __forceinline__ void ldm_x2_t(uint32_t* r, uint32_t addr) {
    asm volatile("ldmatrix.sync.aligned.m8n8.x2.trans.shared.b16 {%0,%1}, [%2];"
                 : "=r"(r[0]), "=r"(r[1]) : "r"(addr));
}
__device__ __forceinline__ void mma_bf16(float* d, const uint32_t* a, const uint32_t* b) {
    asm volatile(
        "mma.sync.aligned.m16n8k16.row.col.f32.bf16.bf16.f32 "
        "{%0,%1,%2,%3}, {%4,%5,%6,%7}, {%8,%9}, {%0,%1,%2,%3};"
        : "+f"(d[0]), "+f"(d[1]), "+f"(d[2]), "+f"(d[3])
        : "r"(a[0]), "r"(a[1]), "r"(a[2]), "r"(a[3]), "r"(b[0]), "r"(b[1]));
}
__device__ __forceinline__ void mma_f16(float* d, const uint32_t* a, const uint32_t* b) {
    asm volatile(
        "mma.sync.aligned.m16n8k16.row.col.f32.f16.f16.f32 "
        "{%0,%1,%2,%3}, {%4,%5,%6,%7}, {%8,%9}, {%0,%1,%2,%3};"
        : "+f"(d[0]), "+f"(d[1]), "+f"(d[2]), "+f"(d[3])
        : "r"(a[0]), "r"(a[1]), "r"(a[2]), "r"(a[3]), "r"(b[0]), "r"(b[1]));
}
__device__ __forceinline__ uint32_t pack_bf16(float x, float y) {
    __nv_bfloat16 bx = __float2bfloat16(x), by = __float2bfloat16(y);
    return (uint32_t)__bfloat16_as_ushort(bx) |
           ((uint32_t)__bfloat16_as_ushort(by) << 16);
}
__device__ __forceinline__ uint32_t cvt_f16x2(float hi, float lo) {
    uint32_t r;
    asm("cvt.rn.f16x2.f32 %0, %1, %2;" : "=r"(r) : "f"(hi), "f"(lo));
    return r;
}
__device__ __forceinline__ float fex2(float x) {
    float r;
    asm("ex2.approx.f32 %0, %1;" : "=f"(r) : "f"(x));
    return r;
}
// fast exp2 on the FMA/ALU pipes: r=rint(f), deg-4 poly, exponent-bit add.
__device__ __forceinline__ float exp2_fast(float f) {
    f = fmaxf(f, -100.f);
    float r = rintf(f);
    float t = f - r;
    float p = 0.009618129f;
    p = fmaf(p, t, 0.055504109f);
    p = fmaf(p, t, 0.240226507f);
    p = fmaf(p, t, 0.693147181f);
    p = fmaf(p, t, 1.0f);
    return __int_as_float(__float_as_int(p) + (((int)r) << 23));
}

// ---------------------------------------------------------------------------
// merged split: fp32 -> bf16 hi/lo for x, Wqkv, Wproj in ONE launch
// ---------------------------------------------------------------------------
constexpr int N_X  = MR_ * C_;       // 3145728
constexpr int N_WQ = C_ * C3_;       // 1769472
constexpr int N_WP = C_ * C_;        // 589824
constexpr int N_TOT4 = (N_X + N_WQ + N_WP) / 4;

__global__ __launch_bounds__(256) void split_all_kernel(
    const float* __restrict__ x, const float* __restrict__ wq,
    const float* __restrict__ wp,
    __nv_bfloat16* __restrict__ xh, __nv_bfloat16* __restrict__ xl,
    __nv_bfloat16* __restrict__ wqh, __nv_bfloat16* __restrict__ wql,
    __nv_bfloat16* __restrict__ wph, __nv_bfloat16* __restrict__ wpl)
{
    int i4 = blockIdx.x * 256 + threadIdx.x;
    if (i4 >= N_TOT4) return;
    int i = i4 * 4;
    const float* src;
    __nv_bfloat16 *hi, *lo;
    if (i < N_X)                 { src = x  + i;                hi = xh  + i;                lo = xl  + i; }
    else if (i < N_X + N_WQ)     { src = wq + (i - N_X);        hi = wqh + (i - N_X);        lo = wql + (i - N_X); }
    else                         { src = wp + (i - N_X - N_WQ); hi = wph + (i - N_X - N_WQ); lo = wpl + (i - N_X - N_WQ); }
    float4 v = *(const float4*)src;
    float f[4] = {v.x, v.y, v.z, v.w};
    float hf[4];
    #pragma unroll
    for (int j = 0; j < 4; j++)
        hf[j] = __bfloat162float(__float2bfloat16(f[j]));
    uint32_t h0 = pack_bf16(f[0], f[1]), h1 = pack_bf16(f[2], f[3]);
    uint32_t l0 = pack_bf16(f[0] - hf[0], f[1] - hf[1]);
    uint32_t l1 = pack_bf16(f[2] - hf[2], f[3] - hf[3]);
    *(uint2*)hi = make_uint2(h0, h1);
    *(uint2*)lo = make_uint2(l0, l1);
}

// ---------------------------------------------------------------------------
// Tensor-core GEMM (bf16 hi/lo x3), 3-stage cp.async pipeline (dyn smem).
// Exact R9 configuration (measured best: QKV 132.7us).
// __launch_bounds__(256, 2) keeps 2 CTAs resident.
// MODE 0: C fp32.   MODE 1: f16 hi/lo split into q/k/v buffers (QKV GEMM).
// ---------------------------------------------------------------------------
constexpr int G_BM = 128, G_BN = 128, G_BK = 16, G_ST = 3;
constexpr int G_ASB = 24, G_BSB = 136;
constexpr int G_ASZ = G_BM * G_ASB;          // elems per A stage
constexpr int G_BSZ = G_BK * G_BSB;          // elems per B stage
constexpr size_t G_SMEM_BYTES =
    (size_t)G_ST * (2 * G_ASZ + 2 * G_BSZ) * 2;   // 62976 B

template <int MODE>
__global__ __launch_bounds__(256, 2) void gemm_bf16x3_kernel(
    const __nv_bfloat16* __restrict__ Ah, const __nv_bfloat16* __restrict__ Al,
    const __nv_bfloat16* __restrict__ Bh, const __nv_bfloat16* __restrict__ Bl,
    const float* __restrict__ bias, float* __restrict__ C,
    __half* __restrict__ qh_o, __half* __restrict__ ql_o,
    __half* __restrict__ kh_o, __half* __restrict__ kl_o,
    __half* __restrict__ vh_o, __half* __restrict__ vl_o,
    int M, int N, int K)
{
    extern __shared__ __nv_bfloat16 smem_dyn[];

    const int tid  = threadIdx.x;
    const int wid  = tid >> 5;
    const int lane = tid & 31;
    const int m0 = blockIdx.y * G_BM;
    const int n0 = blockIdx.x * G_BN;
    const int ry = (wid & 3) * 32;
    const int cx = (wid >> 2) * 64;
    const int g = lane >> 2;
    const int c = lane & 3;

    float acc[2][8][4];
    #pragma unroll
    for (int mi = 0; mi < 2; mi++)
        #pragma unroll
        for (int ni = 0; ni < 8; ni++)
            #pragma unroll
            for (int j = 0; j < 4; j++) acc[mi][ni][j] = 0.f;

    const uint32_t sAhB = smem_u32(smem_dyn);
    const uint32_t sAlB = sAhB + (uint32_t)(G_ST * G_ASZ * 2);
    const uint32_t sBhB = sAlB + (uint32_t)(G_ST * G_ASZ * 2);
    const uint32_t sBlB = sBhB + (uint32_t)(G_ST * G_BSZ * 2);

    const int arow = tid >> 1;
    const int ahalf = tid & 1;
    const int brow = tid >> 4;
    const int bc   = tid & 15;

    auto load_tile = [&](int kt, int st) {
        const int k0 = kt * G_BK;
        const size_t ga = (size_t)(m0 + arow) * K + k0 + ahalf * 8;
        const size_t gb = (size_t)(k0 + brow) * N + n0 + bc * 8;
        const uint32_t oa = (uint32_t)(((st * G_BM + arow) * G_ASB + ahalf * 8) * 2);
        const uint32_t ob = (uint32_t)(((st * G_BK + brow) * G_BSB + bc * 8) * 2);
        cp_async16(sAhB + oa, &Ah[ga]);
        cp_async16(sAlB + oa, &Al[ga]);
        cp_async16(sBhB + ob, &Bh[gb]);
        cp_async16(sBlB + ob, &Bl[gb]);
    };

    const int KT = K / G_BK;
    load_tile(0, 0); cp_commit();
    load_tile(1, 1); cp_commit();

    const int a_r = lane & 15;
    const int a_k = (lane >> 4) * 8;
    const int b_k = (lane & 7) + ((lane >> 3) & 1) * 8;
    const int b_n = (lane >> 4) * 8;

    int st = 0;
    for (int kt = 0; kt < KT; kt++) {
        if (kt + 2 < KT) {
            int st2 = st + 2; if (st2 >= G_ST) st2 -= G_ST;
            load_tile(kt + 2, st2);
        }
        cp_commit();
        cp_wait<2>();
        __syncthreads();

        uint32_t ah[2][4], al[2][4], bh[8][2], bl[8][2];
        #pragma unroll
        for (int mi = 0; mi < 2; mi++) {
            uint32_t off = (uint32_t)(((st * G_BM + ry + mi * 16 + a_r) * G_ASB + a_k) * 2);
            ldm_x4(ah[mi], sAhB + off);
            ldm_x4(al[mi], sAlB + off);
        }
        #pragma unroll
        for (int nb = 0; nb < 4; nb++) {
            uint32_t off = (uint32_t)(((st * G_BK + b_k) * G_BSB + cx + nb * 16 + b_n) * 2);
            uint32_t rh[4], rl[4];
            ldm_x4_t(rh, sBhB + off);
            ldm_x4_t(rl, sBlB + off);
            bh[nb * 2 + 0][0] = rh[0]; bh[nb * 2 + 0][1] = rh[1];
            bh[nb * 2 + 1][0] = rh[2]; bh[nb * 2 + 1][1] = rh[3];
            bl[nb * 2 + 0][0] = rl[0]; bl[nb * 2 + 0][1] = rl[1];
            bl[nb * 2 + 1][0] = rl[2]; bl[nb * 2 + 1][1] = rl[3];
        }
        #pragma unroll
        for (int mi = 0; mi < 2; mi++)
            #pragma unroll
            for (int ni = 0; ni < 8; ni++) {
                mma_bf16(acc[mi][ni], ah[mi], bh[ni]);
                mma_bf16(acc[mi][ni], ah[mi], bl[ni]);
                mma_bf16(acc[mi][ni], al[mi], bh[ni]);
            }
        __syncthreads();
        if (++st >= G_ST) st = 0;
    }

    if (MODE == 0) {
        #pragma unroll
        for (int mi = 0; mi < 2; mi++) {
            #pragma unroll
            for (int ni = 0; ni < 8; ni++) {
                const int rr  = m0 + ry + mi * 16 + g;
                const int ccn = n0 + cx + ni * 8 + c * 2;
                float bx = bias[ccn], by = bias[ccn + 1];
                float2 o0 = make_float2(acc[mi][ni][0] + bx, acc[mi][ni][1] + by);
                float2 o1 = make_float2(acc[mi][ni][2] + bx, acc[mi][ni][3] + by);
                *(float2*)&C[(size_t)rr * N + ccn]       = o0;
                *(float2*)&C[(size_t)(rr + 8) * N + ccn] = o1;
            }
        }
    } else {
        const int sec = n0 / C_;
        const int w0  = n0 - sec * C_;
        __half* hd = (sec == 0) ? qh_o : (sec == 1) ? kh_o : vh_o;
        __half* ld = (sec == 0) ? ql_o : (sec == 1) ? kl_o : vl_o;
        #pragma unroll
        for (int mi = 0; mi < 2; mi++) {
            #pragma unroll
            for (int ni = 0; ni < 8; ni++) {
                const int rr  = m0 + ry + mi * 16 + g;
                const int ccn = n0 + cx + ni * 8 + c * 2;
                const int w   = w0 + cx + ni * 8 + c * 2;
                float bx = bias[ccn], by = bias[ccn + 1];
                float v0 = acc[mi][ni][0] + bx, v1 = acc[mi][ni][1] + by;
                float v2 = acc[mi][ni][2] + bx, v3 = acc[mi][ni][3] + by;
                __half h0 = __float2half_rn(v0), h1 = __float2half_rn(v1);
                __half h2 = __float2half_rn(v2), h3 = __float2half_rn(v3);
                uint32_t hp0 = (uint32_t)__half_as_ushort(h0) |
                               ((uint32_t)__half_as_ushort(h1) << 16);
                uint32_t hp1 = (uint32_t)__half_as_ushort(h2) |
                               ((uint32_t)__half_as_ushort(h3) << 16);
                uint32_t lp0 = cvt_f16x2(v1 - __half2float(h1), v0 - __half2float(h0));
                uint32_t lp1 = cvt_f16x2(v3 - __half2float(h3), v2 - __half2float(h2));
                *(uint32_t*)&hd[(size_t)rr * C_ + w]       = hp0;
                *(uint32_t*)&ld[(size_t)rr * C_ + w]       = lp0;
                *(uint32_t*)&hd[(size_t)(rr + 8) * C_ + w] = hp1;
                *(uint32_t*)&ld[(size_t)(rr + 8) * C_ + w] = lp1;
            }
        }
    }
}

// ---------------------------------------------------------------------------
// Tensor-core flash attention: q-tile 64, 128 threads +
// split-group K/V pipelining (unchanged from R9/R11).
// ---------------------------------------------------------------------------
__global__ __launch_bounds__(128) void attn_mma_kernel(
    const __half* __restrict__ qh_g, const __half* __restrict__ ql_g,
    const __half* __restrict__ kh_g, const __half* __restrict__ kl_g,
    const __half* __restrict__ vh_g, const __half* __restrict__ vl_g,
    __nv_bfloat16* __restrict__ oh, __nv_bfloat16* __restrict__ ol)
{
    __shared__ __align__(16) __half sK[2][64][72];   // hi, lo
    __shared__ __align__(16) __half sV[2][64][88];   // hi, lo (+ones col 64)

    const int tid  = threadIdx.x;
    const int wid  = tid >> 5;
    const int lane = tid & 31;
    const int g  = lane >> 2;
    const int cq = lane & 3;
    const int qt = blockIdx.x;
    const int h  = blockIdx.y;
    const int b  = blockIdx.z;
    const int q0 = qt * 64;
    const float cE = 0.125f * 1.44269504089f;   // scale * log2(e)

    const uint32_t sKhiB = smem_u32(sK);
    const uint32_t sKloB = sKhiB + 64 * 72 * 2;
    const uint32_t sVhiB = smem_u32(sV);
    const uint32_t sVloB = sVhiB + 64 * 88 * 2;

    if (tid < 64) {
        #pragma unroll
        for (int j = 0; j < 8; j++) {
            sV[0][tid][64 + j] = (j == 0) ? __float2half(1.f) : __float2half(0.f);
            sV[1][tid][64 + j] = __float2half(0.f);
        }
    }

    const int a_r = lane & 15;
    const int a_k = (lane >> 4) * 8;

    // ---- stage Q (hi/lo) through sK, load fragments
    {
        const __half* qh_p = qh_g + (size_t)(b * T_ + q0) * C_ + h * HD_;
        const __half* ql_p = ql_g + (size_t)(b * T_ + q0) * C_ + h * HD_;
        #pragma unroll
        for (int i = 0; i < 4; i++) {
            int idx = i * 128 + tid;
            int row = idx >> 3, c16 = idx & 7;
            size_t go = (size_t)row * C_ + c16 * 8;
            uint32_t so = (uint32_t)((row * 72 + c16 * 8) * 2);
            cp_async16(sKhiB + so, qh_p + go);
            cp_async16(sKloB + so, ql_p + go);
        }
        cp_commit();
        cp_wait<0>();
        __syncthreads();
    }
    uint32_t qh[4][4], ql[4][4];
    #pragma unroll
    for (int hs = 0; hs < 4; hs++) {
        uint32_t off = (uint32_t)(((wid * 16 + a_r) * 72 + hs * 16 + a_k) * 2);
        ldm_x4(qh[hs], sKhiB + off);
        ldm_x4(ql[hs], sKloB + off);
    }
    __syncthreads();   // Q fragments read before K fills overwrite sK

    float o[9][4];
    #pragma unroll
    for (int t = 0; t < 9; t++)
        #pragma unroll
        for (int j = 0; j < 4; j++) o[t][j] = 0.f;
    float mi0 = -1e30f, mi1 = -1e30f;

    const int qg0 = q0 + wid * 16 + g;
    const int qg1 = qg0 + 8;
    const int vb_k = (lane & 7) + ((lane >> 3) & 1) * 8;
    const int vb_n = (lane >> 4) * 8;

    auto issue_K = [&](int kt) {
        const size_t gbase = (size_t)(b * T_ + kt * 64) * C_ + h * HD_;
        #pragma unroll
        for (int i = 0; i < 4; i++) {
            int idx = i * 128 + tid;
            int row = idx >> 3, c16 = idx & 7;
            size_t go = gbase + (size_t)row * C_ + c16 * 8;
            uint32_t so = (uint32_t)((row * 72 + c16 * 8) * 2);
            cp_async16(sKhiB + so, kh_g + go);
            cp_async16(sKloB + so, kl_g + go);
        }
    };
    auto issue_V = [&](int kt) {
        const size_t gbase = (size_t)(b * T_ + kt * 64) * C_ + h * HD_;
        #pragma unroll
        for (int i = 0; i < 4; i++) {
            int idx = i * 128 + tid;
            int row = idx >> 3, c16 = idx & 7;
            size_t go = gbase + (size_t)row * C_ + c16 * 8;
            uint32_t so = (uint32_t)((row * 88 + c16 * 8) * 2);
            cp_async16(sVhiB + so, vh_g + go);
            cp_async16(sVloB + so, vl_g + go);
        }
    };

    const int nkt = qt + 1;
    issue_K(0); cp_commit();
    issue_V(0); cp_commit();

    for (int kt = 0; kt < nkt; kt++) {
        cp_wait<1>();        // K_kt ready (V_kt may still be in flight)
        __syncthreads();

        // ---- S = Q @ K^T  (f16 3-term)
        float s[8][4];
        #pragma unroll
        for (int t = 0; t < 8; t++)
            #pragma unroll
            for (int j = 0; j < 4; j++) s[t][j] = 0.f;

        #pragma unroll
        for (int hs = 0; hs < 4; hs++) {
            #pragma unroll
            for (int g16 = 0; g16 < 4; g16++) {
                uint32_t kh4[4], kl4[4];
                uint32_t off = (uint32_t)(((g16 * 16 + a_r) * 72 + hs * 16 + a_k) * 2);
                ldm_x4(kh4, sKhiB + off);
                ldm_x4(kl4, sKloB + off);
                uint32_t bh0[2] = {kh4[0], kh4[2]}, bh1[2] = {kh4[1], kh4[3]};
                uint32_t bl0[2] = {kl4[0], kl4[2]}, bl1[2] = {kl4[1], kl4[3]};
                const int t0 = 2 * g16, t1 = t0 + 1;
                mma_f16(s[t0], qh[hs], bh0);
                mma_f16(s[t0], qh[hs], bl0);
                mma_f16(s[t0], ql[hs], bh0);
                mma_f16(s[t1], qh[hs], bh1);
                mma_f16(s[t1], qh[hs], bl1);
                mma_f16(s[t1], ql[hs], bh1);
            }
        }
        __syncthreads();     // all warps done reading K buffer
        if (kt + 1 < nkt) issue_K(kt + 1);
        cp_commit();         // group: K_{kt+1}

        // ---- causal mask (diagonal chunk only)
        if (kt == qt) {
            const int k0 = kt * 64;
            #pragma unroll
            for (int nt = 0; nt < 8; nt++) {
                const int kgb = k0 + nt * 8 + 2 * cq;
                if (kgb     > qg0) s[nt][0] = -1e30f;
                if (kgb + 1 > qg0) s[nt][1] = -1e30f;
                if (kgb     > qg1) s[nt][2] = -1e30f;
                if (kgb + 1 > qg1) s[nt][3] = -1e30f;
            }
        }

        // ---- online softmax
        float mx0 = mi0, mx1 = mi1;
        #pragma unroll
        for (int nt = 0; nt < 8; nt++) {
            mx0 = fmaxf(mx0, fmaxf(s[nt][0], s[nt][1]));
            mx1 = fmaxf(mx1, fmaxf(s[nt][2], s[nt][3]));
        }
        #pragma unroll
        for (int off = 1; off <= 2; off <<= 1) {
            mx0 = fmaxf(mx0, __shfl_xor_sync(0xffffffffu, mx0, off));
            mx1 = fmaxf(mx1, __shfl_xor_sync(0xffffffffu, mx1, off));
        }
        const float alpha0 = fex2((mi0 - mx0) * cE);
        const float alpha1 = fex2((mi1 - mx1) * cE);
        mi0 = mx0; mi1 = mx1;
        const float b0 = mx0 * cE, b1 = mx1 * cE;

        uint32_t ph[8][2];
        #pragma unroll
        for (int nt = 0; nt < 8; nt++) {
            float e0 = exp2_fast(fmaf(s[nt][0], cE, -b0));
            float e1 = exp2_fast(fmaf(s[nt][1], cE, -b0));
            float e2 = exp2_fast(fmaf(s[nt][2], cE, -b1));
            float e3 = exp2_fast(fmaf(s[nt][3], cE, -b1));
            ph[nt][0] = cvt_f16x2(e1, e0);
            ph[nt][1] = cvt_f16x2(e3, e2);
        }
        #pragma unroll
        for (int t = 0; t < 9; t++) {
            o[t][0] *= alpha0; o[t][1] *= alpha0;
            o[t][2] *= alpha1; o[t][3] *= alpha1;
        }

        cp_wait<1>();        // V_kt ready (K_{kt+1} in flight)
        __syncthreads();

        // ---- O += P @ V  (f16 2-term) + l via ones column
        #pragma unroll
        for (int kb = 0; kb < 4; kb++) {
            uint32_t ap[4] = { ph[2 * kb][0], ph[2 * kb][1],
                               ph[2 * kb + 1][0], ph[2 * kb + 1][1] };
            #pragma unroll
            for (int ng = 0; ng < 4; ng++) {
                uint32_t vh4[4], vl4[4];
                uint32_t off = (uint32_t)(((kb * 16 + vb_k) * 88 + ng * 16 + vb_n) * 2);
                ldm_x4_t(vh4, sVhiB + off);
                ldm_x4_t(vl4, sVloB + off);
                uint32_t vh0[2] = {vh4[0], vh4[1]}, vh1[2] = {vh4[2], vh4[3]};
                uint32_t vl0[2] = {vl4[0], vl4[1]}, vl1[2] = {vl4[2], vl4[3]};
                mma_f16(o[2 * ng],     ap, vh0);
                mma_f16(o[2 * ng],     ap, vl0);
                mma_f16(o[2 * ng + 1], ap, vh1);
                mma_f16(o[2 * ng + 1], ap, vl1);
            }
            uint32_t vo[2];
            uint32_t off1 = (uint32_t)(((kb * 16 + vb_k) * 88 + 64) * 2);
            ldm_x2_t(vo, sVhiB + off1);
            mma_f16(o[8], ap, vo);
        }
        __syncthreads();     // all warps done reading V buffer
        if (kt + 1 < nkt) issue_V(kt + 1);
        cp_commit();         // group: V_{kt+1}
    }

    // ---- epilogue: normalize by l and emit bf16 hi/lo
    const float l0 = __shfl_sync(0xffffffffu, o[8][0], lane & 28);
    const float l1 = __shfl_sync(0xffffffffu, o[8][2], lane & 28);
    const float i0 = 1.f / l0;
    const float i1 = 1.f / l1;
    const size_t r0 = (size_t)(b * T_ + q0 + wid * 16 + g);
    #pragma unroll
    for (int nt = 0; nt < 8; nt++) {
        const int cc = h * HD_ + nt * 8 + 2 * cq;
        float x0 = o[nt][0] * i0, x1 = o[nt][1] * i0;
        float y0 = o[nt][2] * i1, y1 = o[nt][3] * i1;
        float hx0 = __bfloat162float(__float2bfloat16(x0));
        float hx1 = __bfloat162float(__float2bfloat16(x1));
        float hy0 = __bfloat162float(__float2bfloat16(y0));
        float hy1 = __bfloat162float(__float2bfloat16(y1));
        *(uint32_t*)&oh[r0 * C_ + cc]       = pack_bf16(x0, x1);
        *(uint32_t*)&ol[r0 * C_ + cc]       = pack_bf16(x0 - hx0, x1 - hx1);
        *(uint32_t*)&oh[(r0 + 8) * C_ + cc] = pack_bf16(y0, y1);
        *(uint32_t*)&ol[(r0 + 8) * C_ + cc] = pack_bf16(y0 - hy0, y1 - hy1);
    }
}

// ---------------------------------------------------------------------------
extern "C" void kernel_launch(void* const* d_in, const int* in_sizes, int n_in,
                              void* d_out, int out_size)
{
    const float* x     = (const float*)d_in[0];
    const float* Wqkv  = (const float*)d_in[1];
    const float* bqkv  = (const float*)d_in[2];
    const float* Wproj = (const float*)d_in[3];
    const float* bproj = (const float*)d_in[4];
    float* out = (float*)d_out;

    __nv_bfloat16 *xh, *xl, *wqh, *wql, *wph, *wpl, *ah, *al;
    __half *fqh, *fql, *fkh, *fkl, *fvh, *fvl;
    cudaGetSymbolAddress((void**)&xh,  g_xh);
    cudaGetSymbolAddress((void**)&xl,  g_xl);
    cudaGetSymbolAddress((void**)&wqh, g_wqh);
    cudaGetSymbolAddress((void**)&wql, g_wql);
    cudaGetSymbolAddress((void**)&wph, g_wph);
    cudaGetSymbolAddress((void**)&wpl, g_wpl);
    cudaGetSymbolAddress((void**)&ah,  g_ah);
    cudaGetSymbolAddress((void**)&al,  g_al);
    cudaGetSymbolAddress((void**)&fqh, g_fqh);
    cudaGetSymbolAddress((void**)&fql, g_fql);
    cudaGetSymbolAddress((void**)&fkh, g_fkh);
    cudaGetSymbolAddress((void**)&fkl, g_fkl);
    cudaGetSymbolAddress((void**)&fvh, g_fvh);
    cudaGetSymbolAddress((void**)&fvl, g_fvl);

    cudaFuncSetAttribute(gemm_bf16x3_kernel<1>,
                         cudaFuncAttributeMaxDynamicSharedMemorySize,
                         (int)G_SMEM_BYTES);
    cudaFuncSetAttribute(gemm_bf16x3_kernel<0>,
                         cudaFuncAttributeMaxDynamicSharedMemorySize,
                         (int)G_SMEM_BYTES);

    // 0) merged split of x, Wqkv, Wproj into bf16 hi/lo (one launch)
    split_all_kernel<<<(N_TOT4 + 255) / 256, 256>>>(
        x, Wqkv, Wproj, xh, xl, wqh, wql, wph, wpl);

    // 1) QKV GEMM with fused f16 hi/lo q/k/v split epilogue (3-stage)
    gemm_bf16x3_kernel<1><<<dim3(C3_ / 128, MR_ / 128), 256, G_SMEM_BYTES>>>(
        xh, xl, wqh, wql, bqkv, nullptr,
        fqh, fql, fkh, fkl, fvh, fvl, MR_, C3_, C_);

    // 2) pipelined tensor-core flash attention -> bf16 hi/lo [4096, 768]
    attn_mma_kernel<<<dim3(T_ / 64, NH_, B_), 128>>>(
        fqh, fql, fkh, fkl, fvh, fvl, ah, al);

    // 3) out = attn @ Wproj + bproj   [4096, 768]  (3-stage)
    gemm_bf16x3_kernel<0><<<dim3(C_ / 128, MR_ / 128), 256, G_SMEM_BYTES>>>(
        ah, al, wph, wpl, bproj, out,
        nullptr, nullptr, nullptr, nullptr, nullptr, nullptr, MR_, C_, C_);
}

// round 14
// speedup vs baseline: 1.5235x; 1.5235x over previous
#include <cuda_runtime.h>
#include <cuda_bf16.h>
#include <cuda_fp16.h>
#include <cstdint>
#include <math.h>

// Problem constants
constexpr int B_  = 4;
constexpr int T_  = 1024;
constexpr int C_  = 768;
constexpr int NH_ = 12;
constexpr int HD_ = 64;
constexpr int C3_ = 3 * C_;          // 2304
constexpr int MR_ = B_ * T_;         // 4096 rows

// Scratch (static device globals — no allocation)
__device__ __nv_bfloat16 g_xh[(size_t)MR_ * C_];
__device__ __nv_bfloat16 g_xl[(size_t)MR_ * C_];
__device__ __nv_bfloat16 g_wqh[(size_t)C_ * C3_];
__device__ __nv_bfloat16 g_wql[(size_t)C_ * C3_];
__device__ __nv_bfloat16 g_wph[(size_t)C_ * C_];
__device__ __nv_bfloat16 g_wpl[(size_t)C_ * C_];
__device__ __nv_bfloat16 g_ah[(size_t)MR_ * C_];           // attention out hi
__device__ __nv_bfloat16 g_al[(size_t)MR_ * C_];           // attention out lo
// f16 hi/lo splits of q,k,v (written by QKV GEMM epilogue)
__device__ __half g_fqh[(size_t)MR_ * C_];
__device__ __half g_fql[(size_t)MR_ * C_];
__device__ __half g_fkh[(size_t)MR_ * C_];
__device__ __half g_fkl[(size_t)MR_ * C_];
__device__ __half g_fvh[(size_t)MR_ * C_];
__device__ __half g_fvl[(size_t)MR_ * C_];

// ---------------------------------------------------------------------------
// helpers
// ---------------------------------------------------------------------------
__device__ __forceinline__ uint32_t smem_u32(const void* p) {
    uint32_t a;
    asm("{ .reg .u64 t; cvta.to.shared.u64 t, %1; cvt.u32.u64 %0, t; }"
        : "=r"(a) : "l"(p));
    return a;
}
__device__ __forceinline__ void cp_async16(uint32_t saddr, const void* gptr) {
    asm volatile("cp.async.cg.shared.global [%0], [%1], 16;"
                 :: "r"(saddr), "l"(gptr));
}
__device__ __forceinline__ void cp_commit() {
    asm volatile("cp.async.commit_group;");
}
template <int N>
__device__ __forceinline__ void cp_wait() {
    asm volatile("cp.async.wait_group %0;" :: "n"(N));
}
__device__ __forceinline__ void ldm_x4(uint32_t* r, uint32_t addr) {
    asm volatile("ldmatrix.sync.aligned.m8n8.x4.shared.b16 {%0,%1,%2,%3}, [%4];"
                 : "=r"(r[0]), "=r"(r[1]), "=r"(r[2]), "=r"(r[3]) : "r"(addr));
}
__device__ __forceinline__ void ldm_x4_t(uint32_t* r, uint32_t addr) {
    asm volatile("ldmatrix.sync.aligned.m8n8.x4.trans.shared.b16 {%0,%1,%2,%3}, [%4];"
                 : "=r"(r[0]), "=r"(r[1]), "=r"(r[2]), "=r"(r[3]) : "r"(addr));
}
__device__ __forceinline__ void ldm_x2_t(uint32_t* r, uint32_t addr) {
    asm volatile("ldmatrix.sync.aligned.m8n8.x2.trans.shared.b16 {%0,%1}, [%2];"
                 : "=r"(r[0]), "=r"(r[1]) : "r"(addr));
}
__device__ __forceinline__ void mma_bf16(float* d, const uint32_t* a, const uint32_t* b) {
    asm volatile(
        "mma.sync.aligned.m16n8k16.row.col.f32.bf16.bf16.f32 "
        "{%0,%1,%2,%3}, {%4,%5,%6,%7}, {%8,%9}, {%0,%1,%2,%3};"
        : "+f"(d[0]), "+f"(d[1]), "+f"(d[2]), "+f"(d[3])
        : "r"(a[0]), "r"(a[1]), "r"(a[2]), "r"(a[3]), "r"(b[0]), "r"(b[1]));
}
__device__ __forceinline__ void mma_f16(float* d, const uint32_t* a, const uint32_t* b) {
    asm volatile(
        "mma.sync.aligned.m16n8k16.row.col.f32.f16.f16.f32 "
        "{%0,%1,%2,%3}, {%4,%5,%6,%7}, {%8,%9}, {%0,%1,%2,%3};"
        : "+f"(d[0]), "+f"(d[1]), "+f"(d[2]), "+f"(d[3])
        : "r"(a[0]), "r"(a[1]), "r"(a[2]), "r"(a[3]), "r"(b[0]), "r"(b[1]));
}
__device__ __forceinline__ uint32_t pack_bf16(float x, float y) {
    __nv_bfloat16 bx = __float2bfloat16(x), by = __float2bfloat16(y);
    return (uint32_t)__bfloat16_as_ushort(bx) |
           ((uint32_t)__bfloat16_as_ushort(by) << 16);
}
__device__ __forceinline__ uint32_t cvt_f16x2(float hi, float lo) {
    uint32_t r;
    asm("cvt.rn.f16x2.f32 %0, %1, %2;" : "=r"(r) : "f"(hi), "f"(lo));
    return r;
}
__device__ __forceinline__ float fex2(float x) {
    float r;
    asm("ex2.approx.f32 %0, %1;" : "=f"(r) : "f"(x));
    return r;
}
// fast exp2 on the FMA/ALU pipes: r=rint(f), deg-4 poly, exponent-bit add.
__device__ __forceinline__ float exp2_fast(float f) {
    f = fmaxf(f, -100.f);
    float r = rintf(f);
    float t = f - r;
    float p = 0.009618129f;
    p = fmaf(p, t, 0.055504109f);
    p = fmaf(p, t, 0.240226507f);
    p = fmaf(p, t, 0.693147181f);
    p = fmaf(p, t, 1.0f);
    return __int_as_float(__float_as_int(p) + (((int)r) << 23));
}

// ---------------------------------------------------------------------------
// merged split: fp32 -> bf16 hi/lo for x, Wqkv, Wproj in ONE launch
// ---------------------------------------------------------------------------
constexpr int N_X  = MR_ * C_;       // 3145728
constexpr int N_WQ = C_ * C3_;       // 1769472
constexpr int N_WP = C_ * C_;        // 589824
constexpr int N_TOT4 = (N_X + N_WQ + N_WP) / 4;

__global__ __launch_bounds__(256) void split_all_kernel(
    const float* __restrict__ x, const float* __restrict__ wq,
    const float* __restrict__ wp,
    __nv_bfloat16* __restrict__ xh, __nv_bfloat16* __restrict__ xl,
    __nv_bfloat16* __restrict__ wqh, __nv_bfloat16* __restrict__ wql,
    __nv_bfloat16* __restrict__ wph, __nv_bfloat16* __restrict__ wpl)
{
    int i4 = blockIdx.x * 256 + threadIdx.x;
    if (i4 >= N_TOT4) return;
    int i = i4 * 4;
    const float* src;
    __nv_bfloat16 *hi, *lo;
    if (i < N_X)                 { src = x  + i;                hi = xh  + i;                lo = xl  + i; }
    else if (i < N_X + N_WQ)     { src = wq + (i - N_X);        hi = wqh + (i - N_X);        lo = wql + (i - N_X); }
    else                         { src = wp + (i - N_X - N_WQ); hi = wph + (i - N_X - N_WQ); lo = wpl + (i - N_X - N_WQ); }
    float4 v = *(const float4*)src;
    float f[4] = {v.x, v.y, v.z, v.w};
    float hf[4];
    #pragma unroll
    for (int j = 0; j < 4; j++)
        hf[j] = __bfloat162float(__float2bfloat16(f[j]));
    uint32_t h0 = pack_bf16(f[0], f[1]), h1 = pack_bf16(f[2], f[3]);
    uint32_t l0 = pack_bf16(f[0] - hf[0], f[1] - hf[1]);
    uint32_t l1 = pack_bf16(f[2] - hf[2], f[3] - hf[3]);
    *(uint2*)hi = make_uint2(h0, h1);
    *(uint2*)lo = make_uint2(l0, l1);
}

// ---------------------------------------------------------------------------
// Tensor-core GEMM (bf16 hi/lo x3), 3-stage cp.async pipeline (dyn smem).
// MMA issue is TERM-MAJOR: all 16 ah*bh, then 16 ah*bl, then 16 al*bh —
// consecutive MMAs always target different accumulators (dep distance 16).
// Per-accumulator term order (hh->hl->lh) unchanged -> numerics identical.
// __launch_bounds__(256, 2) keeps 2 CTAs resident.
// MODE 0: C fp32.   MODE 1: f16 hi/lo split into q/k/v buffers (QKV GEMM).
// ---------------------------------------------------------------------------
constexpr int G_BM = 128, G_BN = 128, G_BK = 16, G_ST = 3;
constexpr int G_ASB = 24, G_BSB = 136;
constexpr int G_ASZ = G_BM * G_ASB;          // elems per A stage
constexpr int G_BSZ = G_BK * G_BSB;          // elems per B stage
constexpr size_t G_SMEM_BYTES =
    (size_t)G_ST * (2 * G_ASZ + 2 * G_BSZ) * 2;   // 62976 B

template <int MODE>
__global__ __launch_bounds__(256, 2) void gemm_bf16x3_kernel(
    const __nv_bfloat16* __restrict__ Ah, const __nv_bfloat16* __restrict__ Al,
    const __nv_bfloat16* __restrict__ Bh, const __nv_bfloat16* __restrict__ Bl,
    const float* __restrict__ bias, float* __restrict__ C,
    __half* __restrict__ qh_o, __half* __restrict__ ql_o,
    __half* __restrict__ kh_o, __half* __restrict__ kl_o,
    __half* __restrict__ vh_o, __half* __restrict__ vl_o,
    int M, int N, int K)
{
    extern __shared__ __nv_bfloat16 smem_dyn[];

    const int tid  = threadIdx.x;
    const int wid  = tid >> 5;
    const int lane = tid & 31;
    const int m0 = blockIdx.y * G_BM;
    const int n0 = blockIdx.x * G_BN;
    const int ry = (wid & 3) * 32;
    const int cx = (wid >> 2) * 64;
    const int g = lane >> 2;
    const int c = lane & 3;

    float acc[2][8][4];
    #pragma unroll
    for (int mi = 0; mi < 2; mi++)
        #pragma unroll
        for (int ni = 0; ni < 8; ni++)
            #pragma unroll
            for (int j = 0; j < 4; j++) acc[mi][ni][j] = 0.f;

    const uint32_t sAhB = smem_u32(smem_dyn);
    const uint32_t sAlB = sAhB + (uint32_t)(G_ST * G_ASZ * 2);
    const uint32_t sBhB = sAlB + (uint32_t)(G_ST * G_ASZ * 2);
    const uint32_t sBlB = sBhB + (uint32_t)(G_ST * G_BSZ * 2);

    const int arow = tid >> 1;
    const int ahalf = tid & 1;
    const int brow = tid >> 4;
    const int bc   = tid & 15;

    auto load_tile = [&](int kt, int st) {
        const int k0 = kt * G_BK;
        const size_t ga = (size_t)(m0 + arow) * K + k0 + ahalf * 8;
        const size_t gb = (size_t)(k0 + brow) * N + n0 + bc * 8;
        const uint32_t oa = (uint32_t)(((st * G_BM + arow) * G_ASB + ahalf * 8) * 2);
        const uint32_t ob = (uint32_t)(((st * G_BK + brow) * G_BSB + bc * 8) * 2);
        cp_async16(sAhB + oa, &Ah[ga]);
        cp_async16(sAlB + oa, &Al[ga]);
        cp_async16(sBhB + ob, &Bh[gb]);
        cp_async16(sBlB + ob, &Bl[gb]);
    };

    const int KT = K / G_BK;
    load_tile(0, 0); cp_commit();
    load_tile(1, 1); cp_commit();

    const int a_r = lane & 15;
    const int a_k = (lane >> 4) * 8;
    const int b_k = (lane & 7) + ((lane >> 3) & 1) * 8;
    const int b_n = (lane >> 4) * 8;

    int st = 0;
    for (int kt = 0; kt < KT; kt++) {
        if (kt + 2 < KT) {
            int st2 = st + 2; if (st2 >= G_ST) st2 -= G_ST;
            load_tile(kt + 2, st2);
        }
        cp_commit();
        cp_wait<2>();
        __syncthreads();

        uint32_t ah[2][4], al[2][4], bh[8][2], bl[8][2];
        #pragma unroll
        for (int mi = 0; mi < 2; mi++) {
            uint32_t off = (uint32_t)(((st * G_BM + ry + mi * 16 + a_r) * G_ASB + a_k) * 2);
            ldm_x4(ah[mi], sAhB + off);
            ldm_x4(al[mi], sAlB + off);
        }
        #pragma unroll
        for (int nb = 0; nb < 4; nb++) {
            uint32_t off = (uint32_t)(((st * G_BK + b_k) * G_BSB + cx + nb * 16 + b_n) * 2);
            uint32_t rh[4], rl[4];
            ldm_x4_t(rh, sBhB + off);
            ldm_x4_t(rl, sBlB + off);
            bh[nb * 2 + 0][0] = rh[0]; bh[nb * 2 + 0][1] = rh[1];
            bh[nb * 2 + 1][0] = rh[2]; bh[nb * 2 + 1][1] = rh[3];
            bl[nb * 2 + 0][0] = rl[0]; bl[nb * 2 + 0][1] = rl[1];
            bl[nb * 2 + 1][0] = rl[2]; bl[nb * 2 + 1][1] = rl[3];
        }
        // term-major issue: consecutive MMAs hit different accumulators
        #pragma unroll
        for (int mi = 0; mi < 2; mi++)
            #pragma unroll
            for (int ni = 0; ni < 8; ni++)
                mma_bf16(acc[mi][ni], ah[mi], bh[ni]);
        #pragma unroll
        for (int mi = 0; mi < 2; mi++)
            #pragma unroll
            for (int ni = 0; ni < 8; ni++)
                mma_bf16(acc[mi][ni], ah[mi], bl[ni]);
        #pragma unroll
        for (int mi = 0; mi < 2; mi++)
            #pragma unroll
            for (int ni = 0; ni < 8; ni++)
                mma_bf16(acc[mi][ni], al[mi], bh[ni]);
        __syncthreads();
        if (++st >= G_ST) st = 0;
    }

    if (MODE == 0) {
        #pragma unroll
        for (int mi = 0; mi < 2; mi++) {
            #pragma unroll
            for (int ni = 0; ni < 8; ni++) {
                const int rr  = m0 + ry + mi * 16 + g;
                const int ccn = n0 + cx + ni * 8 + c * 2;
                float bx = bias[ccn], by = bias[ccn + 1];
                float2 o0 = make_float2(acc[mi][ni][0] + bx, acc[mi][ni][1] + by);
                float2 o1 = make_float2(acc[mi][ni][2] + bx, acc[mi][ni][3] + by);
                *(float2*)&C[(size_t)rr * N + ccn]       = o0;
                *(float2*)&C[(size_t)(rr + 8) * N + ccn] = o1;
            }
        }
    } else {
        const int sec = n0 / C_;
        const int w0  = n0 - sec * C_;
        __half* hd = (sec == 0) ? qh_o : (sec == 1) ? kh_o : vh_o;
        __half* ld = (sec == 0) ? ql_o : (sec == 1) ? kl_o : vl_o;
        #pragma unroll
        for (int mi = 0; mi < 2; mi++) {
            #pragma unroll
            for (int ni = 0; ni < 8; ni++) {
                const int rr  = m0 + ry + mi * 16 + g;
                const int ccn = n0 + cx + ni * 8 + c * 2;
                const int w   = w0 + cx + ni * 8 + c * 2;
                float bx = bias[ccn], by = bias[ccn + 1];
                float v0 = acc[mi][ni][0] + bx, v1 = acc[mi][ni][1] + by;
                float v2 = acc[mi][ni][2] + bx, v3 = acc[mi][ni][3] + by;
                __half h0 = __float2half_rn(v0), h1 = __float2half_rn(v1);
                __half h2 = __float2half_rn(v2), h3 = __float2half_rn(v3);
                uint32_t hp0 = (uint32_t)__half_as_ushort(h0) |
                               ((uint32_t)__half_as_ushort(h1) << 16);
                uint32_t hp1 = (uint32_t)__half_as_ushort(h2) |
                               ((uint32_t)__half_as_ushort(h3) << 16);
                uint32_t lp0 = cvt_f16x2(v1 - __half2float(h1), v0 - __half2float(h0));
                uint32_t lp1 = cvt_f16x2(v3 - __half2float(h3), v2 - __half2float(h2));
                *(uint32_t*)&hd[(size_t)rr * C_ + w]       = hp0;
                *(uint32_t*)&ld[(size_t)rr * C_ + w]       = lp0;
                *(uint32_t*)&hd[(size_t)(rr + 8) * C_ + w] = hp1;
                *(uint32_t*)&ld[(size_t)(rr + 8) * C_ + w] = lp1;
            }
        }
    }
}

// ---------------------------------------------------------------------------
// Tensor-core flash attention: q-tile 64, 128 threads +
// split-group K/V pipelining. MMA issue interleaved across t0/t1 and o-tiles
// (dependency distance 2 instead of back-to-back same-accumulator).
// ---------------------------------------------------------------------------
__global__ __launch_bounds__(128) void attn_mma_kernel(
    const __half* __restrict__ qh_g, const __half* __restrict__ ql_g,
    const __half* __restrict__ kh_g, const __half* __restrict__ kl_g,
    const __half* __restrict__ vh_g, const __half* __restrict__ vl_g,
    __nv_bfloat16* __restrict__ oh, __nv_bfloat16* __restrict__ ol)
{
    __shared__ __align__(16) __half sK[2][64][72];   // hi, lo
    __shared__ __align__(16) __half sV[2][64][88];   // hi, lo (+ones col 64)

    const int tid  = threadIdx.x;
    const int wid  = tid >> 5;
    const int lane = tid & 31;
    const int g  = lane >> 2;
    const int cq = lane & 3;
    const int qt = blockIdx.x;
    const int h  = blockIdx.y;
    const int b  = blockIdx.z;
    const int q0 = qt * 64;
    const float cE = 0.125f * 1.44269504089f;   // scale * log2(e)

    const uint32_t sKhiB = smem_u32(sK);
    const uint32_t sKloB = sKhiB + 64 * 72 * 2;
    const uint32_t sVhiB = smem_u32(sV);
    const uint32_t sVloB = sVhiB + 64 * 88 * 2;

    if (tid < 64) {
        #pragma unroll
        for (int j = 0; j < 8; j++) {
            sV[0][tid][64 + j] = (j == 0) ? __float2half(1.f) : __float2half(0.f);
            sV[1][tid][64 + j] = __float2half(0.f);
        }
    }

    const int a_r = lane & 15;
    const int a_k = (lane >> 4) * 8;

    // ---- stage Q (hi/lo) through sK, load fragments
    {
        const __half* qh_p = qh_g + (size_t)(b * T_ + q0) * C_ + h * HD_;
        const __half* ql_p = ql_g + (size_t)(b * T_ + q0) * C_ + h * HD_;
        #pragma unroll
        for (int i = 0; i < 4; i++) {
            int idx = i * 128 + tid;
            int row = idx >> 3, c16 = idx & 7;
            size_t go = (size_t)row * C_ + c16 * 8;
            uint32_t so = (uint32_t)((row * 72 + c16 * 8) * 2);
            cp_async16(sKhiB + so, qh_p + go);
            cp_async16(sKloB + so, ql_p + go);
        }
        cp_commit();
        cp_wait<0>();
        __syncthreads();
    }
    uint32_t qh[4][4], ql[4][4];
    #pragma unroll
    for (int hs = 0; hs < 4; hs++) {
        uint32_t off = (uint32_t)(((wid * 16 + a_r) * 72 + hs * 16 + a_k) * 2);
        ldm_x4(qh[hs], sKhiB + off);
        ldm_x4(ql[hs], sKloB + off);
    }
    __syncthreads();   // Q fragments read before K fills overwrite sK

    float o[9][4];
    #pragma unroll
    for (int t = 0; t < 9; t++)
        #pragma unroll
        for (int j = 0; j < 4; j++) o[t][j] = 0.f;
    float mi0 = -1e30f, mi1 = -1e30f;

    const int qg0 = q0 + wid * 16 + g;
    const int qg1 = qg0 + 8;
    const int vb_k = (lane & 7) + ((lane >> 3) & 1) * 8;
    const int vb_n = (lane >> 4) * 8;

    auto issue_K = [&](int kt) {
        const size_t gbase = (size_t)(b * T_ + kt * 64) * C_ + h * HD_;
        #pragma unroll
        for (int i = 0; i < 4; i++) {
            int idx = i * 128 + tid;
            int row = idx >> 3, c16 = idx & 7;
            size_t go = gbase + (size_t)row * C_ + c16 * 8;
            uint32_t so = (uint32_t)((row * 72 + c16 * 8) * 2);
            cp_async16(sKhiB + so, kh_g + go);
            cp_async16(sKloB + so, kl_g + go);
        }
    };
    auto issue_V = [&](int kt) {
        const size_t gbase = (size_t)(b * T_ + kt * 64) * C_ + h * HD_;
        #pragma unroll
        for (int i = 0; i < 4; i++) {
            int idx = i * 128 + tid;
            int row = idx >> 3, c16 = idx & 7;
            size_t go = gbase + (size_t)row * C_ + c16 * 8;
            uint32_t so = (uint32_t)((row * 88 + c16 * 8) * 2);
            cp_async16(sVhiB + so, vh_g + go);
            cp_async16(sVloB + so, vl_g + go);
        }
    };

    const int nkt = qt + 1;
    issue_K(0); cp_commit();
    issue_V(0); cp_commit();

    for (int kt = 0; kt < nkt; kt++) {
        cp_wait<1>();        // K_kt ready (V_kt may still be in flight)
        __syncthreads();

        // ---- S = Q @ K^T  (f16 3-term), interleaved t0/t1 issue
        float s[8][4];
        #pragma unroll
        for (int t = 0; t < 8; t++)
            #pragma unroll
            for (int j = 0; j < 4; j++) s[t][j] = 0.f;

        #pragma unroll
        for (int hs = 0; hs < 4; hs++) {
            #pragma unroll
            for (int g16 = 0; g16 < 4; g16++) {
                uint32_t kh4[4], kl4[4];
                uint32_t off = (uint32_t)(((g16 * 16 + a_r) * 72 + hs * 16 + a_k) * 2);
                ldm_x4(kh4, sKhiB + off);
                ldm_x4(kl4, sKloB + off);
                uint32_t bh0[2] = {kh4[0], kh4[2]}, bh1[2] = {kh4[1], kh4[3]};
                uint32_t bl0[2] = {kl4[0], kl4[2]}, bl1[2] = {kl4[1], kl4[3]};
                const int t0 = 2 * g16, t1 = t0 + 1;
                mma_f16(s[t0], qh[hs], bh0);
                mma_f16(s[t1], qh[hs], bh1);
                mma_f16(s[t0], qh[hs], bl0);
                mma_f16(s[t1], qh[hs], bl1);
                mma_f16(s[t0], ql[hs], bh0);
                mma_f16(s[t1], ql[hs], bh1);
            }
        }
        __syncthreads();     // all warps done reading K buffer
        if (kt + 1 < nkt) issue_K(kt + 1);
        cp_commit();         // group: K_{kt+1}

        // ---- causal mask (diagonal chunk only)
        if (kt == qt) {
            const int k0 = kt * 64;
            #pragma unroll
            for (int nt = 0; nt < 8; nt++) {
                const int kgb = k0 + nt * 8 + 2 * cq;
                if (kgb     > qg0) s[nt][0] = -1e30f;
                if (kgb + 1 > qg0) s[nt][1] = -1e30f;
                if (kgb     > qg1) s[nt][2] = -1e30f;
                if (kgb + 1 > qg1) s[nt][3] = -1e30f;
            }
        }

        // ---- online softmax
        float mx0 = mi0, mx1 = mi1;
        #pragma unroll
        for (int nt = 0; nt < 8; nt++) {
            mx0 = fmaxf(mx0, fmaxf(s[nt][0], s[nt][1]));
            mx1 = fmaxf(mx1, fmaxf(s[nt][2], s[nt][3]));
        }
        #pragma unroll
        for (int off = 1; off <= 2; off <<= 1) {
            mx0 = fmaxf(mx0, __shfl_xor_sync(0xffffffffu, mx0, off));
            mx1 = fmaxf(mx1, __shfl_xor_sync(0xffffffffu, mx1, off));
        }
        const float alpha0 = fex2((mi0 - mx0) * cE);
        const float alpha1 = fex2((mi1 - mx1) * cE);
        mi0 = mx0; mi1 = mx1;
        const float b0 = mx0 * cE, b1 = mx1 * cE;

        uint32_t ph[8][2];
        #pragma unroll
        for (int nt = 0; nt < 8; nt++) {
            float e0 = exp2_fast(fmaf(s[nt][0], cE, -b0));
            float e1 = exp2_fast(fmaf(s[nt][1], cE, -b0));
            float e2 = exp2_fast(fmaf(s[nt][2], cE, -b1));
            float e3 = exp2_fast(fmaf(s[nt][3], cE, -b1));
            ph[nt][0] = cvt_f16x2(e1, e0);
            ph[nt][1] = cvt_f16x2(e3, e2);
        }
        #pragma unroll
        for (int t = 0; t < 9; t++) {
            o[t][0] *= alpha0; o[t][1] *= alpha0;
            o[t][2] *= alpha1; o[t][3] *= alpha1;
        }

        cp_wait<1>();        // V_kt ready (K_{kt+1} in flight)
        __syncthreads();

        // ---- O += P @ V  (f16 2-term) + l via ones column, interleaved
        #pragma unroll
        for (int kb = 0; kb < 4; kb++) {
            uint32_t ap[4] = { ph[2 * kb][0], ph[2 * kb][1],
                               ph[2 * kb + 1][0], ph[2 * kb + 1][1] };
            #pragma unroll
            for (int ng = 0; ng < 4; ng++) {
                uint32_t vh4[4], vl4[4];
                uint32_t off = (uint32_t)(((kb * 16 + vb_k) * 88 + ng * 16 + vb_n) * 2);
                ldm_x4_t(vh4, sVhiB + off);
                ldm_x4_t(vl4, sVloB + off);
                uint32_t vh0[2] = {vh4[0], vh4[1]}, vh1[2] = {vh4[2], vh4[3]};
                uint32_t vl0[2] = {vl4[0], vl4[1]}, vl1[2] = {vl4[2], vl4[3]};
                mma_f16(o[2 * ng],     ap, vh0);
                mma_f16(o[2 * ng + 1], ap, vh1);
                mma_f16(o[2 * ng],     ap, vl0);
                mma_f16(o[2 * ng + 1], ap, vl1);
            }
            uint32_t vo[2];
            uint32_t off1 = (uint32_t)(((kb * 16 + vb_k) * 88 + 64) * 2);
            ldm_x2_t(vo, sVhiB + off1);
            mma_f16(o[8], ap, vo);
        }
        __syncthreads();     // all warps done reading V buffer
        if (kt + 1 < nkt) issue_V(kt + 1);
        cp_commit();         // group: V_{kt+1}
    }

    // ---- epilogue: normalize by l and emit bf16 hi/lo
    const float l0 = __shfl_sync(0xffffffffu, o[8][0], lane & 28);
    const float l1 = __shfl_sync(0xffffffffu, o[8][2], lane & 28);
    const float i0 = 1.f / l0;
    const float i1 = 1.f / l1;
    const size_t r0 = (size_t)(b * T_ + q0 + wid * 16 + g);
    #pragma unroll
    for (int nt = 0; nt < 8; nt++) {
        const int cc = h * HD_ + nt * 8 + 2 * cq;
        float x0 = o[nt][0] * i0, x1 = o[nt][1] * i0;
        float y0 = o[nt][2] * i1, y1 = o[nt][3] * i1;
        float hx0 = __bfloat162float(__float2bfloat16(x0));
        float hx1 = __bfloat162float(__float2bfloat16(x1));
        float hy0 = __bfloat162float(__float2bfloat16(y0));
        float hy1 = __bfloat162float(__float2bfloat16(y1));
        *(uint32_t*)&oh[r0 * C_ + cc]       = pack_bf16(x0, x1);
        *(uint32_t*)&ol[r0 * C_ + cc]       = pack_bf16(x0 - hx0, x1 - hx1);
        *(uint32_t*)&oh[(r0 + 8) * C_ + cc] = pack_bf16(y0, y1);
        *(uint32_t*)&ol[(r0 + 8) * C_ + cc] = pack_bf16(y0 - hy0, y1 - hy1);
    }
}

// ---------------------------------------------------------------------------
extern "C" void kernel_launch(void* const* d_in, const int* in_sizes, int n_in,
                              void* d_out, int out_size)
{
    const float* x     = (const float*)d_in[0];
    const float* Wqkv  = (const float*)d_in[1];
    const float* bqkv  = (const float*)d_in[2];
    const float* Wproj = (const float*)d_in[3];
    const float* bproj = (const float*)d_in[4];
    float* out = (float*)d_out;

    __nv_bfloat16 *xh, *xl, *wqh, *wql, *wph, *wpl, *ah, *al;
    __half *fqh, *fql, *fkh, *fkl, *fvh, *fvl;
    cudaGetSymbolAddress((void**)&xh,  g_xh);
    cudaGetSymbolAddress((void**)&xl,  g_xl);
    cudaGetSymbolAddress((void**)&wqh, g_wqh);
    cudaGetSymbolAddress((void**)&wql, g_wql);
    cudaGetSymbolAddress((void**)&wph, g_wph);
    cudaGetSymbolAddress((void**)&wpl, g_wpl);
    cudaGetSymbolAddress((void**)&ah,  g_ah);
    cudaGetSymbolAddress((void**)&al,  g_al);
    cudaGetSymbolAddress((void**)&fqh, g_fqh);
    cudaGetSymbolAddress((void**)&fql, g_fql);
    cudaGetSymbolAddress((void**)&fkh, g_fkh);
    cudaGetSymbolAddress((void**)&fkl, g_fkl);
    cudaGetSymbolAddress((void**)&fvh, g_fvh);
    cudaGetSymbolAddress((void**)&fvl, g_fvl);

    cudaFuncSetAttribute(gemm_bf16x3_kernel<1>,
                         cudaFuncAttributeMaxDynamicSharedMemorySize,
                         (int)G_SMEM_BYTES);
    cudaFuncSetAttribute(gemm_bf16x3_kernel<0>,
                         cudaFuncAttributeMaxDynamicSharedMemorySize,
                         (int)G_SMEM_BYTES);

    // 0) merged split of x, Wqkv, Wproj into bf16 hi/lo (one launch)
    split_all_kernel<<<(N_TOT4 + 255) / 256, 256>>>(
        x, Wqkv, Wproj, xh, xl, wqh, wql, wph, wpl);

    // 1) QKV GEMM with fused f16 hi/lo q/k/v split epilogue (3-stage)
    gemm_bf16x3_kernel<1><<<dim3(C3_ / 128, MR_ / 128), 256, G_SMEM_BYTES>>>(
        xh, xl, wqh, wql, bqkv, nullptr,
        fqh, fql, fkh, fkl, fvh, fvl, MR_, C3_, C_);

    // 2) pipelined tensor-core flash attention -> bf16 hi/lo [4096, 768]
    attn_mma_kernel<<<dim3(T_ / 64, NH_, B_), 128>>>(
        fqh, fql, fkh, fkl, fvh, fvl, ah, al);

    // 3) out = attn @ Wproj + bproj   [4096, 768]  (3-stage)
    gemm_bf16x3_kernel<0><<<dim3(C_ / 128, MR_ / 128), 256, G_SMEM_BYTES>>>(
        ah, al, wph, wpl, bproj, out,
        nullptr, nullptr, nullptr, nullptr, nullptr, nullptr, MR_, C_, C_);
}

// round 15
// speedup vs baseline: 2.0824x; 1.3669x over previous
#include <cuda_runtime.h>
#include <cuda_bf16.h>
#include <cuda_fp16.h>
#include <cstdint>
#include <math.h>

// Problem constants
constexpr int B_  = 4;
constexpr int T_  = 1024;
constexpr int C_  = 768;
constexpr int NH_ = 12;
constexpr int HD_ = 64;
constexpr int C3_ = 3 * C_;          // 2304
constexpr int MR_ = B_ * T_;         // 4096 rows

// Scratch (static device globals — no allocation)
__device__ __half g_xh[(size_t)MR_ * C_];                  // x as f16 (hi only)
__device__ __half g_wqh[(size_t)C_ * C3_];
__device__ __half g_wql[(size_t)C_ * C3_];
__device__ __half g_wph[(size_t)C_ * C_];
__device__ __half g_wpl[(size_t)C_ * C_];
__device__ __half g_oa[(size_t)MR_ * C_];                  // attention out (f16)
// f16 hi/lo splits of q,k,v (written by QKV GEMM epilogue)
__device__ __half g_fqh[(size_t)MR_ * C_];
__device__ __half g_fql[(size_t)MR_ * C_];
__device__ __half g_fkh[(size_t)MR_ * C_];
__device__ __half g_fkl[(size_t)MR_ * C_];
__device__ __half g_fvh[(size_t)MR_ * C_];
__device__ __half g_fvl[(size_t)MR_ * C_];

// ---------------------------------------------------------------------------
// helpers
// ---------------------------------------------------------------------------
__device__ __forceinline__ uint32_t smem_u32(const void* p) {
    uint32_t a;
    asm("{ .reg .u64 t; cvta.to.shared.u64 t, %1; cvt.u32.u64 %0, t; }"
        : "=r"(a) : "l"(p));
    return a;
}
__device__ __forceinline__ void cp_async16(uint32_t saddr, const void* gptr) {
    asm volatile("cp.async.cg.shared.global [%0], [%1], 16;"
                 :: "r"(saddr), "l"(gptr));
}
__device__ __forceinline__ void cp_commit() {
    asm volatile("cp.async.commit_group;");
}
template <int N>
__device__ __forceinline__ void cp_wait() {
    asm volatile("cp.async.wait_group %0;" :: "n"(N));
}
__device__ __forceinline__ void ldm_x4(uint32_t* r, uint32_t addr) {
    asm volatile("ldmatrix.sync.aligned.m8n8.x4.shared.b16 {%0,%1,%2,%3}, [%4];"
                 : "=r"(r[0]), "=r"(r[1]), "=r"(r[2]), "=r"(r[3]) : "r"(addr));
}
__device__ __forceinline__ void ldm_x4_t(uint32_t* r, uint32_t addr) {
    asm volatile("ldmatrix.sync.aligned.m8n8.x4.trans.shared.b16 {%0,%1,%2,%3}, [%4];"
                 : "=r"(r[0]), "=r"(r[1]), "=r"(r[2]), "=r"(r[3]) : "r"(addr));
}
__device__ __forceinline__ void ldm_x2_t(uint32_t* r, uint32_t addr) {
    asm volatile("ldmatrix.sync.aligned.m8n8.x2.trans.shared.b16 {%0,%1}, [%2];"
                 : "=r"(r[0]), "=r"(r[1]) : "r"(addr));
}
__device__ __forceinline__ void mma_f16(float* d, const uint32_t* a, const uint32_t* b) {
    asm volatile(
        "mma.sync.aligned.m16n8k16.row.col.f32.f16.f16.f32 "
        "{%0,%1,%2,%3}, {%4,%5,%6,%7}, {%8,%9}, {%0,%1,%2,%3};"
        : "+f"(d[0]), "+f"(d[1]), "+f"(d[2]), "+f"(d[3])
        : "r"(a[0]), "r"(a[1]), "r"(a[2]), "r"(a[3]), "r"(b[0]), "r"(b[1]));
}
__device__ __forceinline__ uint32_t cvt_f16x2(float hi, float lo) {
    uint32_t r;
    asm("cvt.rn.f16x2.f32 %0, %1, %2;" : "=r"(r) : "f"(hi), "f"(lo));
    return r;
}
__device__ __forceinline__ float fex2(float x) {
    float r;
    asm("ex2.approx.f32 %0, %1;" : "=f"(r) : "f"(x));
    return r;
}
// fast exp2 on the FMA/ALU pipes: r=rint(f), deg-4 poly, exponent-bit add.
__device__ __forceinline__ float exp2_fast(float f) {
    f = fmaxf(f, -100.f);
    float r = rintf(f);
    float t = f - r;
    float p = 0.009618129f;
    p = fmaf(p, t, 0.055504109f);
    p = fmaf(p, t, 0.240226507f);
    p = fmaf(p, t, 0.693147181f);
    p = fmaf(p, t, 1.0f);
    return __int_as_float(__float_as_int(p) + (((int)r) << 23));
}
__device__ __forceinline__ uint32_t pack_f16(float x, float y) {
    return cvt_f16x2(y, x);   // lo half = x, hi half = y
}

// ---------------------------------------------------------------------------
// merged split: x -> f16 (hi only); Wqkv, Wproj -> f16 hi + f16 lo(residual)
// ---------------------------------------------------------------------------
constexpr int N_X  = MR_ * C_;       // 3145728
constexpr int N_WQ = C_ * C3_;       // 1769472
constexpr int N_WP = C_ * C_;        // 589824
constexpr int N_TOT4 = (N_X + N_WQ + N_WP) / 4;

__global__ __launch_bounds__(256) void split_all_kernel(
    const float* __restrict__ x, const float* __restrict__ wq,
    const float* __restrict__ wp,
    __half* __restrict__ xh,
    __half* __restrict__ wqh, __half* __restrict__ wql,
    __half* __restrict__ wph, __half* __restrict__ wpl)
{
    int i4 = blockIdx.x * 256 + threadIdx.x;
    if (i4 >= N_TOT4) return;
    int i = i4 * 4;
    if (i < N_X) {
        float4 v = *(const float4*)&x[i];
        *(uint2*)&xh[i] = make_uint2(pack_f16(v.x, v.y), pack_f16(v.z, v.w));
        return;
    }
    const float* src;
    __half *hi, *lo;
    if (i < N_X + N_WQ) { src = wq + (i - N_X);        hi = wqh + (i - N_X);        lo = wql + (i - N_X); }
    else                { src = wp + (i - N_X - N_WQ); hi = wph + (i - N_X - N_WQ); lo = wpl + (i - N_X - N_WQ); }
    float4 v = *(const float4*)src;
    float f[4] = {v.x, v.y, v.z, v.w};
    __half hh[4];
    float res[4];
    #pragma unroll
    for (int j = 0; j < 4; j++) {
        hh[j] = __float2half_rn(f[j]);
        res[j] = f[j] - __half2float(hh[j]);
    }
    uint32_t h0 = (uint32_t)__half_as_ushort(hh[0]) | ((uint32_t)__half_as_ushort(hh[1]) << 16);
    uint32_t h1 = (uint32_t)__half_as_ushort(hh[2]) | ((uint32_t)__half_as_ushort(hh[3]) << 16);
    *(uint2*)hi = make_uint2(h0, h1);
    *(uint2*)lo = make_uint2(pack_f16(res[0], res[1]), pack_f16(res[2], res[3]));
}

// ---------------------------------------------------------------------------
// Tensor-core GEMM (f16 x2: D = Ah*Bh + Ah*Bl), 3-stage cp.async pipeline.
// A is a single f16 stream; B is f16 hi/lo. Term-major MMA issue
// (16x hh then 16x hl -> dep distance 16). __launch_bounds__(256,2).
// MODE 0: C fp32 + bias.  MODE 1: f16 hi/lo split into q/k/v buffers.
// ---------------------------------------------------------------------------
constexpr int G_BM = 128, G_BN = 128, G_BK = 16, G_ST = 3;
constexpr int G_ASB = 24, G_BSB = 136;
constexpr int G_ASZ = G_BM * G_ASB;          // elems per A stage (3072)
constexpr int G_BSZ = G_BK * G_BSB;          // elems per B stage (2176)
constexpr size_t G_SMEM_BYTES =
    (size_t)G_ST * (G_ASZ + 2 * G_BSZ) * 2;  // 44544 B

template <int MODE>
__global__ __launch_bounds__(256, 2) void gemm_f16x2_kernel(
    const __half* __restrict__ Ah,
    const __half* __restrict__ Bh, const __half* __restrict__ Bl,
    const float* __restrict__ bias, float* __restrict__ C,
    __half* __restrict__ qh_o, __half* __restrict__ ql_o,
    __half* __restrict__ kh_o, __half* __restrict__ kl_o,
    __half* __restrict__ vh_o, __half* __restrict__ vl_o,
    int M, int N, int K)
{
    extern __shared__ __half smem_dyn[];

    const int tid  = threadIdx.x;
    const int wid  = tid >> 5;
    const int lane = tid & 31;
    const int m0 = blockIdx.y * G_BM;
    const int n0 = blockIdx.x * G_BN;
    const int ry = (wid & 3) * 32;
    const int cx = (wid >> 2) * 64;
    const int g = lane >> 2;
    const int c = lane & 3;

    float acc[2][8][4];
    #pragma unroll
    for (int mi = 0; mi < 2; mi++)
        #pragma unroll
        for (int ni = 0; ni < 8; ni++)
            #pragma unroll
            for (int j = 0; j < 4; j++) acc[mi][ni][j] = 0.f;

    const uint32_t sAhB = smem_u32(smem_dyn);
    const uint32_t sBhB = sAhB + (uint32_t)(G_ST * G_ASZ * 2);
    const uint32_t sBlB = sBhB + (uint32_t)(G_ST * G_BSZ * 2);

    const int arow = tid >> 1;
    const int ahalf = tid & 1;
    const int brow = tid >> 4;
    const int bc   = tid & 15;

    auto load_tile = [&](int kt, int st) {
        const int k0 = kt * G_BK;
        const size_t ga = (size_t)(m0 + arow) * K + k0 + ahalf * 8;
        const size_t gb = (size_t)(k0 + brow) * N + n0 + bc * 8;
        const uint32_t oa = (uint32_t)(((st * G_BM + arow) * G_ASB + ahalf * 8) * 2);
        const uint32_t ob = (uint32_t)(((st * G_BK + brow) * G_BSB + bc * 8) * 2);
        cp_async16(sAhB + oa, &Ah[ga]);
        cp_async16(sBhB + ob, &Bh[gb]);
        cp_async16(sBlB + ob, &Bl[gb]);
    };

    const int KT = K / G_BK;
    load_tile(0, 0); cp_commit();
    load_tile(1, 1); cp_commit();

    const int a_r = lane & 15;
    const int a_k = (lane >> 4) * 8;
    const int b_k = (lane & 7) + ((lane >> 3) & 1) * 8;
    const int b_n = (lane >> 4) * 8;

    int st = 0;
    for (int kt = 0; kt < KT; kt++) {
        if (kt + 2 < KT) {
            int st2 = st + 2; if (st2 >= G_ST) st2 -= G_ST;
            load_tile(kt + 2, st2);
        }
        cp_commit();
        cp_wait<2>();
        __syncthreads();

        uint32_t ah[2][4], bh[8][2], bl[8][2];
        #pragma unroll
        for (int mi = 0; mi < 2; mi++) {
            uint32_t off = (uint32_t)(((st * G_BM + ry + mi * 16 + a_r) * G_ASB + a_k) * 2);
            ldm_x4(ah[mi], sAhB + off);
        }
        #pragma unroll
        for (int nb = 0; nb < 4; nb++) {
            uint32_t off = (uint32_t)(((st * G_BK + b_k) * G_BSB + cx + nb * 16 + b_n) * 2);
            uint32_t rh[4], rl[4];
            ldm_x4_t(rh, sBhB + off);
            ldm_x4_t(rl, sBlB + off);
            bh[nb * 2 + 0][0] = rh[0]; bh[nb * 2 + 0][1] = rh[1];
            bh[nb * 2 + 1][0] = rh[2]; bh[nb * 2 + 1][1] = rh[3];
            bl[nb * 2 + 0][0] = rl[0]; bl[nb * 2 + 0][1] = rl[1];
            bl[nb * 2 + 1][0] = rl[2]; bl[nb * 2 + 1][1] = rl[3];
        }
        // term-major: consecutive MMAs hit different accumulators
        #pragma unroll
        for (int mi = 0; mi < 2; mi++)
            #pragma unroll
            for (int ni = 0; ni < 8; ni++)
                mma_f16(acc[mi][ni], ah[mi], bh[ni]);
        #pragma unroll
        for (int mi = 0; mi < 2; mi++)
            #pragma unroll
            for (int ni = 0; ni < 8; ni++)
                mma_f16(acc[mi][ni], ah[mi], bl[ni]);
        __syncthreads();
        if (++st >= G_ST) st = 0;
    }

    if (MODE == 0) {
        #pragma unroll
        for (int mi = 0; mi < 2; mi++) {
            #pragma unroll
            for (int ni = 0; ni < 8; ni++) {
                const int rr  = m0 + ry + mi * 16 + g;
                const int ccn = n0 + cx + ni * 8 + c * 2;
                float bx = bias[ccn], by = bias[ccn + 1];
                float2 o0 = make_float2(acc[mi][ni][0] + bx, acc[mi][ni][1] + by);
                float2 o1 = make_float2(acc[mi][ni][2] + bx, acc[mi][ni][3] + by);
                *(float2*)&C[(size_t)rr * N + ccn]       = o0;
                *(float2*)&C[(size_t)(rr + 8) * N + ccn] = o1;
            }
        }
    } else {
        const int sec = n0 / C_;
        const int w0  = n0 - sec * C_;
        __half* hd = (sec == 0) ? qh_o : (sec == 1) ? kh_o : vh_o;
        __half* ld = (sec == 0) ? ql_o : (sec == 1) ? kl_o : vl_o;
        #pragma unroll
        for (int mi = 0; mi < 2; mi++) {
            #pragma unroll
            for (int ni = 0; ni < 8; ni++) {
                const int rr  = m0 + ry + mi * 16 + g;
                const int ccn = n0 + cx + ni * 8 + c * 2;
                const int w   = w0 + cx + ni * 8 + c * 2;
                float bx = bias[ccn], by = bias[ccn + 1];
                float v0 = acc[mi][ni][0] + bx, v1 = acc[mi][ni][1] + by;
                float v2 = acc[mi][ni][2] + bx, v3 = acc[mi][ni][3] + by;
                __half h0 = __float2half_rn(v0), h1 = __float2half_rn(v1);
                __half h2 = __float2half_rn(v2), h3 = __float2half_rn(v3);
                uint32_t hp0 = (uint32_t)__half_as_ushort(h0) |
                               ((uint32_t)__half_as_ushort(h1) << 16);
                uint32_t hp1 = (uint32_t)__half_as_ushort(h2) |
                               ((uint32_t)__half_as_ushort(h3) << 16);
                uint32_t lp0 = cvt_f16x2(v1 - __half2float(h1), v0 - __half2float(h0));
                uint32_t lp1 = cvt_f16x2(v3 - __half2float(h3), v2 - __half2float(h2));
                *(uint32_t*)&hd[(size_t)rr * C_ + w]       = hp0;
                *(uint32_t*)&ld[(size_t)rr * C_ + w]       = lp0;
                *(uint32_t*)&hd[(size_t)(rr + 8) * C_ + w] = hp1;
                *(uint32_t*)&ld[(size_t)(rr + 8) * C_ + w] = lp1;
            }
        }
    }
}

// ---------------------------------------------------------------------------
// Tensor-core flash attention: q-tile 64, 128 threads +
// split-group K/V pipelining; interleaved MMA issue (R14).
// Epilogue now writes a single f16 output stream (proj GEMM's A operand).
// ---------------------------------------------------------------------------
__global__ __launch_bounds__(128) void attn_mma_kernel(
    const __half* __restrict__ qh_g, const __half* __restrict__ ql_g,
    const __half* __restrict__ kh_g, const __half* __restrict__ kl_g,
    const __half* __restrict__ vh_g, const __half* __restrict__ vl_g,
    __half* __restrict__ oa)
{
    __shared__ __align__(16) __half sK[2][64][72];   // hi, lo
    __shared__ __align__(16) __half sV[2][64][88];   // hi, lo (+ones col 64)

    const int tid  = threadIdx.x;
    const int wid  = tid >> 5;
    const int lane = tid & 31;
    const int g  = lane >> 2;
    const int cq = lane & 3;
    const int qt = blockIdx.x;
    const int h  = blockIdx.y;
    const int b  = blockIdx.z;
    const int q0 = qt * 64;
    const float cE = 0.125f * 1.44269504089f;   // scale * log2(e)

    const uint32_t sKhiB = smem_u32(sK);
    const uint32_t sKloB = sKhiB + 64 * 72 * 2;
    const uint32_t sVhiB = smem_u32(sV);
    const uint32_t sVloB = sVhiB + 64 * 88 * 2;

    if (tid < 64) {
        #pragma unroll
        for (int j = 0; j < 8; j++) {
            sV[0][tid][64 + j] = (j == 0) ? __float2half(1.f) : __float2half(0.f);
            sV[1][tid][64 + j] = __float2half(0.f);
        }
    }

    const int a_r = lane & 15;
    const int a_k = (lane >> 4) * 8;

    // ---- stage Q (hi/lo) through sK, load fragments
    {
        const __half* qh_p = qh_g + (size_t)(b * T_ + q0) * C_ + h * HD_;
        const __half* ql_p = ql_g + (size_t)(b * T_ + q0) * C_ + h * HD_;
        #pragma unroll
        for (int i = 0; i < 4; i++) {
            int idx = i * 128 + tid;
            int row = idx >> 3, c16 = idx & 7;
            size_t go = (size_t)row * C_ + c16 * 8;
            uint32_t so = (uint32_t)((row * 72 + c16 * 8) * 2);
            cp_async16(sKhiB + so, qh_p + go);
            cp_async16(sKloB + so, ql_p + go);
        }
        cp_commit();
        cp_wait<0>();
        __syncthreads();
    }
    uint32_t qh[4][4], ql[4][4];
    #pragma unroll
    for (int hs = 0; hs < 4; hs++) {
        uint32_t off = (uint32_t)(((wid * 16 + a_r) * 72 + hs * 16 + a_k) * 2);
        ldm_x4(qh[hs], sKhiB + off);
        ldm_x4(ql[hs], sKloB + off);
    }
    __syncthreads();   // Q fragments read before K fills overwrite sK

    float o[9][4];
    #pragma unroll
    for (int t = 0; t < 9; t++)
        #pragma unroll
        for (int j = 0; j < 4; j++) o[t][j] = 0.f;
    float mi0 = -1e30f, mi1 = -1e30f;

    const int qg0 = q0 + wid * 16 + g;
    const int qg1 = qg0 + 8;
    const int vb_k = (lane & 7) + ((lane >> 3) & 1) * 8;
    const int vb_n = (lane >> 4) * 8;

    auto issue_K = [&](int kt) {
        const size_t gbase = (size_t)(b * T_ + kt * 64) * C_ + h * HD_;
        #pragma unroll
        for (int i = 0; i < 4; i++) {
            int idx = i * 128 + tid;
            int row = idx >> 3, c16 = idx & 7;
            size_t go = gbase + (size_t)row * C_ + c16 * 8;
            uint32_t so = (uint32_t)((row * 72 + c16 * 8) * 2);
            cp_async16(sKhiB + so, kh_g + go);
            cp_async16(sKloB + so, kl_g + go);
        }
    };
    auto issue_V = [&](int kt) {
        const size_t gbase = (size_t)(b * T_ + kt * 64) * C_ + h * HD_;
        #pragma unroll
        for (int i = 0; i < 4; i++) {
            int idx = i * 128 + tid;
            int row = idx >> 3, c16 = idx & 7;
            size_t go = gbase + (size_t)row * C_ + c16 * 8;
            uint32_t so = (uint32_t)((row * 88 + c16 * 8) * 2);
            cp_async16(sVhiB + so, vh_g + go);
            cp_async16(sVloB + so, vl_g + go);
        }
    };

    const int nkt = qt + 1;
    issue_K(0); cp_commit();
    issue_V(0); cp_commit();

    for (int kt = 0; kt < nkt; kt++) {
        cp_wait<1>();        // K_kt ready (V_kt may still be in flight)
        __syncthreads();

        // ---- S = Q @ K^T  (f16 3-term), interleaved t0/t1 issue
        float s[8][4];
        #pragma unroll
        for (int t = 0; t < 8; t++)
            #pragma unroll
            for (int j = 0; j < 4; j++) s[t][j] = 0.f;

        #pragma unroll
        for (int hs = 0; hs < 4; hs++) {
            #pragma unroll
            for (int g16 = 0; g16 < 4; g16++) {
                uint32_t kh4[4], kl4[4];
                uint32_t off = (uint32_t)(((g16 * 16 + a_r) * 72 + hs * 16 + a_k) * 2);
                ldm_x4(kh4, sKhiB + off);
                ldm_x4(kl4, sKloB + off);
                uint32_t bh0[2] = {kh4[0], kh4[2]}, bh1[2] = {kh4[1], kh4[3]};
                uint32_t bl0[2] = {kl4[0], kl4[2]}, bl1[2] = {kl4[1], kl4[3]};
                const int t0 = 2 * g16, t1 = t0 + 1;
                mma_f16(s[t0], qh[hs], bh0);
                mma_f16(s[t1], qh[hs], bh1);
                mma_f16(s[t0], qh[hs], bl0);
                mma_f16(s[t1], qh[hs], bl1);
                mma_f16(s[t0], ql[hs], bh0);
                mma_f16(s[t1], ql[hs], bh1);
            }
        }
        __syncthreads();     // all warps done reading K buffer
        if (kt + 1 < nkt) issue_K(kt + 1);
        cp_commit();         // group: K_{kt+1}

        // ---- causal mask (diagonal chunk only)
        if (kt == qt) {
            const int k0 = kt * 64;
            #pragma unroll
            for (int nt = 0; nt < 8; nt++) {
                const int kgb = k0 + nt * 8 + 2 * cq;
                if (kgb     > qg0) s[nt][0] = -1e30f;
                if (kgb + 1 > qg0) s[nt][1] = -1e30f;
                if (kgb     > qg1) s[nt][2] = -1e30f;
                if (kgb + 1 > qg1) s[nt][3] = -1e30f;
            }
        }

        // ---- online softmax
        float mx0 = mi0, mx1 = mi1;
        #pragma unroll
        for (int nt = 0; nt < 8; nt++) {
            mx0 = fmaxf(mx0, fmaxf(s[nt][0], s[nt][1]));
            mx1 = fmaxf(mx1, fmaxf(s[nt][2], s[nt][3]));
        }
        #pragma unroll
        for (int off = 1; off <= 2; off <<= 1) {
            mx0 = fmaxf(mx0, __shfl_xor_sync(0xffffffffu, mx0, off));
            mx1 = fmaxf(mx1, __shfl_xor_sync(0xffffffffu, mx1, off));
        }
        const float alpha0 = fex2((mi0 - mx0) * cE);
        const float alpha1 = fex2((mi1 - mx1) * cE);
        mi0 = mx0; mi1 = mx1;
        const float b0 = mx0 * cE, b1 = mx1 * cE;

        uint32_t ph[8][2];
        #pragma unroll
        for (int nt = 0; nt < 8; nt++) {
            float e0 = exp2_fast(fmaf(s[nt][0], cE, -b0));
            float e1 = exp2_fast(fmaf(s[nt][1], cE, -b0));
            float e2 = exp2_fast(fmaf(s[nt][2], cE, -b1));
            float e3 = exp2_fast(fmaf(s[nt][3], cE, -b1));
            ph[nt][0] = cvt_f16x2(e1, e0);
            ph[nt][1] = cvt_f16x2(e3, e2);
        }
        #pragma unroll
        for (int t = 0; t < 9; t++) {
            o[t][0] *= alpha0; o[t][1] *= alpha0;
            o[t][2] *= alpha1; o[t][3] *= alpha1;
        }

        cp_wait<1>();        // V_kt ready (K_{kt+1} in flight)
        __syncthreads();

        // ---- O += P @ V  (f16 2-term) + l via ones column, interleaved
        #pragma unroll
        for (int kb = 0; kb < 4; kb++) {
            uint32_t ap[4] = { ph[2 * kb][0], ph[2 * kb][1],
                               ph[2 * kb + 1][0], ph[2 * kb + 1][1] };
            #pragma unroll
            for (int ng = 0; ng < 4; ng++) {
                uint32_t vh4[4], vl4[4];
                uint32_t off = (uint32_t)(((kb * 16 + vb_k) * 88 + ng * 16 + vb_n) * 2);
                ldm_x4_t(vh4, sVhiB + off);
                ldm_x4_t(vl4, sVloB + off);
                uint32_t vh0[2] = {vh4[0], vh4[1]}, vh1[2] = {vh4[2], vh4[3]};
                uint32_t vl0[2] = {vl4[0], vl4[1]}, vl1[2] = {vl4[2], vl4[3]};
                mma_f16(o[2 * ng],     ap, vh0);
                mma_f16(o[2 * ng + 1], ap, vh1);
                mma_f16(o[2 * ng],     ap, vl0);
                mma_f16(o[2 * ng + 1], ap, vl1);
            }
            uint32_t vo[2];
            uint32_t off1 = (uint32_t)(((kb * 16 + vb_k) * 88 + 64) * 2);
            ldm_x2_t(vo, sVhiB + off1);
            mma_f16(o[8], ap, vo);
        }
        __syncthreads();     // all warps done reading V buffer
        if (kt + 1 < nkt) issue_V(kt + 1);
        cp_commit();         // group: V_{kt+1}
    }

    // ---- epilogue: normalize by l, emit f16 (single stream)
    const float l0 = __shfl_sync(0xffffffffu, o[8][0], lane & 28);
    const float l1 = __shfl_sync(0xffffffffu, o[8][2], lane & 28);
    const float i0 = 1.f / l0;
    const float i1 = 1.f / l1;
    const size_t r0 = (size_t)(b * T_ + q0 + wid * 16 + g);
    #pragma unroll
    for (int nt = 0; nt < 8; nt++) {
        const int cc = h * HD_ + nt * 8 + 2 * cq;
        *(uint32_t*)&oa[r0 * C_ + cc] =
            cvt_f16x2(o[nt][1] * i0, o[nt][0] * i0);
        *(uint32_t*)&oa[(r0 + 8) * C_ + cc] =
            cvt_f16x2(o[nt][3] * i1, o[nt][2] * i1);
    }
}

// ---------------------------------------------------------------------------
extern "C" void kernel_launch(void* const* d_in, const int* in_sizes, int n_in,
                              void* d_out, int out_size)
{
    const float* x     = (const float*)d_in[0];
    const float* Wqkv  = (const float*)d_in[1];
    const float* bqkv  = (const float*)d_in[2];
    const float* Wproj = (const float*)d_in[3];
    const float* bproj = (const float*)d_in[4];
    float* out = (float*)d_out;

    __half *xh, *wqh, *wql, *wph, *wpl, *oa;
    __half *fqh, *fql, *fkh, *fkl, *fvh, *fvl;
    cudaGetSymbolAddress((void**)&xh,  g_xh);
    cudaGetSymbolAddress((void**)&wqh, g_wqh);
    cudaGetSymbolAddress((void**)&wql, g_wql);
    cudaGetSymbolAddress((void**)&wph, g_wph);
    cudaGetSymbolAddress((void**)&wpl, g_wpl);
    cudaGetSymbolAddress((void**)&oa,  g_oa);
    cudaGetSymbolAddress((void**)&fqh, g_fqh);
    cudaGetSymbolAddress((void**)&fql, g_fql);
    cudaGetSymbolAddress((void**)&fkh, g_fkh);
    cudaGetSymbolAddress((void**)&fkl, g_fkl);
    cudaGetSymbolAddress((void**)&fvh, g_fvh);
    cudaGetSymbolAddress((void**)&fvl, g_fvl);

    cudaFuncSetAttribute(gemm_f16x2_kernel<1>,
                         cudaFuncAttributeMaxDynamicSharedMemorySize,
                         (int)G_SMEM_BYTES);
    cudaFuncSetAttribute(gemm_f16x2_kernel<0>,
                         cudaFuncAttributeMaxDynamicSharedMemorySize,
                         (int)G_SMEM_BYTES);

    // 0) merged split: x -> f16; Wqkv, Wproj -> f16 hi/lo (one launch)
    split_all_kernel<<<(N_TOT4 + 255) / 256, 256>>>(
        x, Wqkv, Wproj, xh, wqh, wql, wph, wpl);

    // 1) QKV GEMM (f16x2) with fused f16 hi/lo q/k/v split epilogue
    gemm_f16x2_kernel<1><<<dim3(C3_ / 128, MR_ / 128), 256, G_SMEM_BYTES>>>(
        xh, wqh, wql, bqkv, nullptr,
        fqh, fql, fkh, fkl, fvh, fvl, MR_, C3_, C_);

    // 2) pipelined tensor-core flash attention -> f16 [4096, 768]
    attn_mma_kernel<<<dim3(T_ / 64, NH_, B_), 128>>>(
        fqh, fql, fkh, fkl, fvh, fvl, oa);

    // 3) out = attn @ Wproj + bproj   [4096, 768]  (f16x2)
    gemm_f16x2_kernel<0><<<dim3(C_ / 128, MR_ / 128), 256, G_SMEM_BYTES>>>(
        oa, wph, wpl, bproj, out,
        nullptr, nullptr, nullptr, nullptr, nullptr, nullptr, MR_, C_, C_);
}

// round 16
// speedup vs baseline: 2.1361x; 1.0258x over previous
#include <cuda_runtime.h>
#include <cuda_bf16.h>
#include <cuda_fp16.h>
#include <cstdint>
#include <math.h>

// Problem constants
constexpr int B_  = 4;
constexpr int T_  = 1024;
constexpr int C_  = 768;
constexpr int NH_ = 12;
constexpr int HD_ = 64;
constexpr int C3_ = 3 * C_;          // 2304
constexpr int MR_ = B_ * T_;         // 4096 rows

// Scratch (static device globals — no allocation)
__device__ __half g_xh[(size_t)MR_ * C_];                  // x as f16 (hi only)
__device__ __half g_wqh[(size_t)C_ * C3_];
__device__ __half g_wql[(size_t)C_ * C3_];
__device__ __half g_wph[(size_t)C_ * C_];
__device__ __half g_wpl[(size_t)C_ * C_];
__device__ __half g_oa[(size_t)MR_ * C_];                  // attention out (f16)
// f16 splits of q,k,v (q: hi only; k,v: hi/lo) — written by QKV GEMM epilogue
__device__ __half g_fqh[(size_t)MR_ * C_];
__device__ __half g_fql[(size_t)MR_ * C_];                 // written, unused
__device__ __half g_fkh[(size_t)MR_ * C_];
__device__ __half g_fkl[(size_t)MR_ * C_];
__device__ __half g_fvh[(size_t)MR_ * C_];
__device__ __half g_fvl[(size_t)MR_ * C_];

// ---------------------------------------------------------------------------
// helpers
// ---------------------------------------------------------------------------
__device__ __forceinline__ uint32_t smem_u32(const void* p) {
    uint32_t a;
    asm("{ .reg .u64 t; cvta.to.shared.u64 t, %1; cvt.u32.u64 %0, t; }"
        : "=r"(a) : "l"(p));
    return a;
}
__device__ __forceinline__ void cp_async16(uint32_t saddr, const void* gptr) {
    asm volatile("cp.async.cg.shared.global [%0], [%1], 16;"
                 :: "r"(saddr), "l"(gptr));
}
__device__ __forceinline__ void cp_commit() {
    asm volatile("cp.async.commit_group;");
}
template <int N>
__device__ __forceinline__ void cp_wait() {
    asm volatile("cp.async.wait_group %0;" :: "n"(N));
}
__device__ __forceinline__ void ldm_x4(uint32_t* r, uint32_t addr) {
    asm volatile("ldmatrix.sync.aligned.m8n8.x4.shared.b16 {%0,%1,%2,%3}, [%4];"
                 : "=r"(r[0]), "=r"(r[1]), "=r"(r[2]), "=r"(r[3]) : "r"(addr));
}
__device__ __forceinline__ void ldm_x4_t(uint32_t* r, uint32_t addr) {
    asm volatile("ldmatrix.sync.aligned.m8n8.x4.trans.shared.b16 {%0,%1,%2,%3}, [%4];"
                 : "=r"(r[0]), "=r"(r[1]), "=r"(r[2]), "=r"(r[3]) : "r"(addr));
}
__device__ __forceinline__ void ldm_x2_t(uint32_t* r, uint32_t addr) {
    asm volatile("ldmatrix.sync.aligned.m8n8.x2.trans.shared.b16 {%0,%1}, [%2];"
                 : "=r"(r[0]), "=r"(r[1]) : "r"(addr));
}
__device__ __forceinline__ void mma_f16(float* d, const uint32_t* a, const uint32_t* b) {
    asm volatile(
        "mma.sync.aligned.m16n8k16.row.col.f32.f16.f16.f32 "
        "{%0,%1,%2,%3}, {%4,%5,%6,%7}, {%8,%9}, {%0,%1,%2,%3};"
        : "+f"(d[0]), "+f"(d[1]), "+f"(d[2]), "+f"(d[3])
        : "r"(a[0]), "r"(a[1]), "r"(a[2]), "r"(a[3]), "r"(b[0]), "r"(b[1]));
}
__device__ __forceinline__ uint32_t cvt_f16x2(float hi, float lo) {
    uint32_t r;
    asm("cvt.rn.f16x2.f32 %0, %1, %2;" : "=r"(r) : "f"(hi), "f"(lo));
    return r;
}
__device__ __forceinline__ float fex2(float x) {
    float r;
    asm("ex2.approx.f32 %0, %1;" : "=f"(r) : "f"(x));
    return r;
}
// fast exp2 on the FMA/ALU pipes: r=rint(f), deg-4 poly, exponent-bit add.
__device__ __forceinline__ float exp2_fast(float f) {
    f = fmaxf(f, -100.f);
    float r = rintf(f);
    float t = f - r;
    float p = 0.009618129f;
    p = fmaf(p, t, 0.055504109f);
    p = fmaf(p, t, 0.240226507f);
    p = fmaf(p, t, 0.693147181f);
    p = fmaf(p, t, 1.0f);
    return __int_as_float(__float_as_int(p) + (((int)r) << 23));
}
__device__ __forceinline__ uint32_t pack_f16(float x, float y) {
    return cvt_f16x2(y, x);   // lo half = x, hi half = y
}

// ---------------------------------------------------------------------------
// merged split: x -> f16 (hi only); Wqkv, Wproj -> f16 hi + f16 lo(residual)
// ---------------------------------------------------------------------------
constexpr int N_X  = MR_ * C_;       // 3145728
constexpr int N_WQ = C_ * C3_;       // 1769472
constexpr int N_WP = C_ * C_;        // 589824
constexpr int N_TOT4 = (N_X + N_WQ + N_WP) / 4;

__global__ __launch_bounds__(256) void split_all_kernel(
    const float* __restrict__ x, const float* __restrict__ wq,
    const float* __restrict__ wp,
    __half* __restrict__ xh,
    __half* __restrict__ wqh, __half* __restrict__ wql,
    __half* __restrict__ wph, __half* __restrict__ wpl)
{
    int i4 = blockIdx.x * 256 + threadIdx.x;
    if (i4 >= N_TOT4) return;
    int i = i4 * 4;
    if (i < N_X) {
        float4 v = *(const float4*)&x[i];
        *(uint2*)&xh[i] = make_uint2(pack_f16(v.x, v.y), pack_f16(v.z, v.w));
        return;
    }
    const float* src;
    __half *hi, *lo;
    if (i < N_X + N_WQ) { src = wq + (i - N_X);        hi = wqh + (i - N_X);        lo = wql + (i - N_X); }
    else                { src = wp + (i - N_X - N_WQ); hi = wph + (i - N_X - N_WQ); lo = wpl + (i - N_X - N_WQ); }
    float4 v = *(const float4*)src;
    float f[4] = {v.x, v.y, v.z, v.w};
    __half hh[4];
    float res[4];
    #pragma unroll
    for (int j = 0; j < 4; j++) {
        hh[j] = __float2half_rn(f[j]);
        res[j] = f[j] - __half2float(hh[j]);
    }
    uint32_t h0 = (uint32_t)__half_as_ushort(hh[0]) | ((uint32_t)__half_as_ushort(hh[1]) << 16);
    uint32_t h1 = (uint32_t)__half_as_ushort(hh[2]) | ((uint32_t)__half_as_ushort(hh[3]) << 16);
    *(uint2*)hi = make_uint2(h0, h1);
    *(uint2*)lo = make_uint2(pack_f16(res[0], res[1]), pack_f16(res[2], res[3]));
}

// ---------------------------------------------------------------------------
// Tensor-core GEMM (f16 x2: D = Ah*Bh + Ah*Bl), 3-stage cp.async pipeline.
// Term-major MMA issue. __launch_bounds__(256,2).
// MODE 0: C fp32 + bias.  MODE 1: f16 split into q/k/v buffers
//         (q section: hi only; k/v: hi+lo).
// ---------------------------------------------------------------------------
constexpr int G_BM = 128, G_BN = 128, G_BK = 16, G_ST = 3;
constexpr int G_ASB = 24, G_BSB = 136;
constexpr int G_ASZ = G_BM * G_ASB;
constexpr int G_BSZ = G_BK * G_BSB;
constexpr size_t G_SMEM_BYTES =
    (size_t)G_ST * (G_ASZ + 2 * G_BSZ) * 2;  // 44544 B

template <int MODE>
__global__ __launch_bounds__(256, 2) void gemm_f16x2_kernel(
    const __half* __restrict__ Ah,
    const __half* __restrict__ Bh, const __half* __restrict__ Bl,
    const float* __restrict__ bias, float* __restrict__ C,
    __half* __restrict__ qh_o, __half* __restrict__ ql_o,
    __half* __restrict__ kh_o, __half* __restrict__ kl_o,
    __half* __restrict__ vh_o, __half* __restrict__ vl_o,
    int M, int N, int K)
{
    extern __shared__ __half smem_dyn[];

    const int tid  = threadIdx.x;
    const int wid  = tid >> 5;
    const int lane = tid & 31;
    const int m0 = blockIdx.y * G_BM;
    const int n0 = blockIdx.x * G_BN;
    const int ry = (wid & 3) * 32;
    const int cx = (wid >> 2) * 64;
    const int g = lane >> 2;
    const int c = lane & 3;

    float acc[2][8][4];
    #pragma unroll
    for (int mi = 0; mi < 2; mi++)
        #pragma unroll
        for (int ni = 0; ni < 8; ni++)
            #pragma unroll
            for (int j = 0; j < 4; j++) acc[mi][ni][j] = 0.f;

    const uint32_t sAhB = smem_u32(smem_dyn);
    const uint32_t sBhB = sAhB + (uint32_t)(G_ST * G_ASZ * 2);
    const uint32_t sBlB = sBhB + (uint32_t)(G_ST * G_BSZ * 2);

    const int arow = tid >> 1;
    const int ahalf = tid & 1;
    const int brow = tid >> 4;
    const int bc   = tid & 15;

    auto load_tile = [&](int kt, int st) {
        const int k0 = kt * G_BK;
        const size_t ga = (size_t)(m0 + arow) * K + k0 + ahalf * 8;
        const size_t gb = (size_t)(k0 + brow) * N + n0 + bc * 8;
        const uint32_t oa = (uint32_t)(((st * G_BM + arow) * G_ASB + ahalf * 8) * 2);
        const uint32_t ob = (uint32_t)(((st * G_BK + brow) * G_BSB + bc * 8) * 2);
        cp_async16(sAhB + oa, &Ah[ga]);
        cp_async16(sBhB + ob, &Bh[gb]);
        cp_async16(sBlB + ob, &Bl[gb]);
    };

    const int KT = K / G_BK;
    load_tile(0, 0); cp_commit();
    load_tile(1, 1); cp_commit();

    const int a_r = lane & 15;
    const int a_k = (lane >> 4) * 8;
    const int b_k = (lane & 7) + ((lane >> 3) & 1) * 8;
    const int b_n = (lane >> 4) * 8;

    int st = 0;
    for (int kt = 0; kt < KT; kt++) {
        if (kt + 2 < KT) {
            int st2 = st + 2; if (st2 >= G_ST) st2 -= G_ST;
            load_tile(kt + 2, st2);
        }
        cp_commit();
        cp_wait<2>();
        __syncthreads();

        uint32_t ah[2][4], bh[8][2], bl[8][2];
        #pragma unroll
        for (int mi = 0; mi < 2; mi++) {
            uint32_t off = (uint32_t)(((st * G_BM + ry + mi * 16 + a_r) * G_ASB + a_k) * 2);
            ldm_x4(ah[mi], sAhB + off);
        }
        #pragma unroll
        for (int nb = 0; nb < 4; nb++) {
            uint32_t off = (uint32_t)(((st * G_BK + b_k) * G_BSB + cx + nb * 16 + b_n) * 2);
            uint32_t rh[4], rl[4];
            ldm_x4_t(rh, sBhB + off);
            ldm_x4_t(rl, sBlB + off);
            bh[nb * 2 + 0][0] = rh[0]; bh[nb * 2 + 0][1] = rh[1];
            bh[nb * 2 + 1][0] = rh[2]; bh[nb * 2 + 1][1] = rh[3];
            bl[nb * 2 + 0][0] = rl[0]; bl[nb * 2 + 0][1] = rl[1];
            bl[nb * 2 + 1][0] = rl[2]; bl[nb * 2 + 1][1] = rl[3];
        }
        // term-major: consecutive MMAs hit different accumulators
        #pragma unroll
        for (int mi = 0; mi < 2; mi++)
            #pragma unroll
            for (int ni = 0; ni < 8; ni++)
                mma_f16(acc[mi][ni], ah[mi], bh[ni]);
        #pragma unroll
        for (int mi = 0; mi < 2; mi++)
            #pragma unroll
            for (int ni = 0; ni < 8; ni++)
                mma_f16(acc[mi][ni], ah[mi], bl[ni]);
        __syncthreads();
        if (++st >= G_ST) st = 0;
    }

    if (MODE == 0) {
        #pragma unroll
        for (int mi = 0; mi < 2; mi++) {
            #pragma unroll
            for (int ni = 0; ni < 8; ni++) {
                const int rr  = m0 + ry + mi * 16 + g;
                const int ccn = n0 + cx + ni * 8 + c * 2;
                float bx = bias[ccn], by = bias[ccn + 1];
                float2 o0 = make_float2(acc[mi][ni][0] + bx, acc[mi][ni][1] + by);
                float2 o1 = make_float2(acc[mi][ni][2] + bx, acc[mi][ni][3] + by);
                *(float2*)&C[(size_t)rr * N + ccn]       = o0;
                *(float2*)&C[(size_t)(rr + 8) * N + ccn] = o1;
            }
        }
    } else {
        const int sec = n0 / C_;
        const int w0  = n0 - sec * C_;
        __half* hd = (sec == 0) ? qh_o : (sec == 1) ? kh_o : vh_o;
        __half* ld = (sec == 0) ? ql_o : (sec == 1) ? kl_o : vl_o;
        const bool need_lo = (sec != 0);   // q consumer uses hi only
        #pragma unroll
        for (int mi = 0; mi < 2; mi++) {
            #pragma unroll
            for (int ni = 0; ni < 8; ni++) {
                const int rr  = m0 + ry + mi * 16 + g;
                const int ccn = n0 + cx + ni * 8 + c * 2;
                const int w   = w0 + cx + ni * 8 + c * 2;
                float bx = bias[ccn], by = bias[ccn + 1];
                float v0 = acc[mi][ni][0] + bx, v1 = acc[mi][ni][1] + by;
                float v2 = acc[mi][ni][2] + bx, v3 = acc[mi][ni][3] + by;
                __half h0 = __float2half_rn(v0), h1 = __float2half_rn(v1);
                __half h2 = __float2half_rn(v2), h3 = __float2half_rn(v3);
                uint32_t hp0 = (uint32_t)__half_as_ushort(h0) |
                               ((uint32_t)__half_as_ushort(h1) << 16);
                uint32_t hp1 = (uint32_t)__half_as_ushort(h2) |
                               ((uint32_t)__half_as_ushort(h3) << 16);
                *(uint32_t*)&hd[(size_t)rr * C_ + w]       = hp0;
                *(uint32_t*)&hd[(size_t)(rr + 8) * C_ + w] = hp1;
                if (need_lo) {
                    uint32_t lp0 = cvt_f16x2(v1 - __half2float(h1), v0 - __half2float(h0));
                    uint32_t lp1 = cvt_f16x2(v3 - __half2float(h3), v2 - __half2float(h2));
                    *(uint32_t*)&ld[(size_t)rr * C_ + w]       = lp0;
                    *(uint32_t*)&ld[(size_t)(rr + 8) * C_ + w] = lp1;
                }
            }
        }
    }
}

// ---------------------------------------------------------------------------
// Tensor-core flash attention: q-tile 64, 128 threads +
// split-group K/V pipelining. Q single f16; K f16 hi/lo (S 2-term);
// V f16 hi/lo (PV 2-term). Interleaved MMA issue.
// ---------------------------------------------------------------------------
__global__ __launch_bounds__(128) void attn_mma_kernel(
    const __half* __restrict__ qh_g,
    const __half* __restrict__ kh_g, const __half* __restrict__ kl_g,
    const __half* __restrict__ vh_g, const __half* __restrict__ vl_g,
    __half* __restrict__ oa)
{
    __shared__ __align__(16) __half sK[2][64][72];   // hi, lo
    __shared__ __align__(16) __half sV[2][64][88];   // hi, lo (+ones col 64)

    const int tid  = threadIdx.x;
    const int wid  = tid >> 5;
    const int lane = tid & 31;
    const int g  = lane >> 2;
    const int cq = lane & 3;
    const int qt = blockIdx.x;
    const int h  = blockIdx.y;
    const int b  = blockIdx.z;
    const int q0 = qt * 64;
    const float cE = 0.125f * 1.44269504089f;   // scale * log2(e)

    const uint32_t sKhiB = smem_u32(sK);
    const uint32_t sKloB = sKhiB + 64 * 72 * 2;
    const uint32_t sVhiB = smem_u32(sV);
    const uint32_t sVloB = sVhiB + 64 * 88 * 2;

    if (tid < 64) {
        #pragma unroll
        for (int j = 0; j < 8; j++) {
            sV[0][tid][64 + j] = (j == 0) ? __float2half(1.f) : __float2half(0.f);
            sV[1][tid][64 + j] = __float2half(0.f);
        }
    }

    const int a_r = lane & 15;
    const int a_k = (lane >> 4) * 8;

    // ---- stage Q (hi only) through sK-hi, load fragments
    {
        const __half* qh_p = qh_g + (size_t)(b * T_ + q0) * C_ + h * HD_;
        #pragma unroll
        for (int i = 0; i < 4; i++) {
            int idx = i * 128 + tid;
            int row = idx >> 3, c16 = idx & 7;
            size_t go = (size_t)row * C_ + c16 * 8;
            uint32_t so = (uint32_t)((row * 72 + c16 * 8) * 2);
            cp_async16(sKhiB + so, qh_p + go);
        }
        cp_commit();
        cp_wait<0>();
        __syncthreads();
    }
    uint32_t qh[4][4];
    #pragma unroll
    for (int hs = 0; hs < 4; hs++) {
        uint32_t off = (uint32_t)(((wid * 16 + a_r) * 72 + hs * 16 + a_k) * 2);
        ldm_x4(qh[hs], sKhiB + off);
    }
    __syncthreads();   // Q fragments read before K fills overwrite sK

    float o[9][4];
    #pragma unroll
    for (int t = 0; t < 9; t++)
        #pragma unroll
        for (int j = 0; j < 4; j++) o[t][j] = 0.f;
    float mi0 = -1e30f, mi1 = -1e30f;

    const int qg0 = q0 + wid * 16 + g;
    const int qg1 = qg0 + 8;
    const int vb_k = (lane & 7) + ((lane >> 3) & 1) * 8;
    const int vb_n = (lane >> 4) * 8;

    auto issue_K = [&](int kt) {
        const size_t gbase = (size_t)(b * T_ + kt * 64) * C_ + h * HD_;
        #pragma unroll
        for (int i = 0; i < 4; i++) {
            int idx = i * 128 + tid;
            int row = idx >> 3, c16 = idx & 7;
            size_t go = gbase + (size_t)row * C_ + c16 * 8;
            uint32_t so = (uint32_t)((row * 72 + c16 * 8) * 2);
            cp_async16(sKhiB + so, kh_g + go);
            cp_async16(sKloB + so, kl_g + go);
        }
    };
    auto issue_V = [&](int kt) {
        const size_t gbase = (size_t)(b * T_ + kt * 64) * C_ + h * HD_;
        #pragma unroll
        for (int i = 0; i < 4; i++) {
            int idx = i * 128 + tid;
            int row = idx >> 3, c16 = idx & 7;
            size_t go = gbase + (size_t)row * C_ + c16 * 8;
            uint32_t so = (uint32_t)((row * 88 + c16 * 8) * 2);
            cp_async16(sVhiB + so, vh_g + go);
            cp_async16(sVloB + so, vl_g + go);
        }
    };

    const int nkt = qt + 1;
    issue_K(0); cp_commit();
    issue_V(0); cp_commit();

    for (int kt = 0; kt < nkt; kt++) {
        cp_wait<1>();        // K_kt ready (V_kt may still be in flight)
        __syncthreads();

        // ---- S = Q @ K^T  (f16 2-term: qh*kh + qh*kl), interleaved
        float s[8][4];
        #pragma unroll
        for (int t = 0; t < 8; t++)
            #pragma unroll
            for (int j = 0; j < 4; j++) s[t][j] = 0.f;

        #pragma unroll
        for (int hs = 0; hs < 4; hs++) {
            #pragma unroll
            for (int g16 = 0; g16 < 4; g16++) {
                uint32_t kh4[4], kl4[4];
                uint32_t off = (uint32_t)(((g16 * 16 + a_r) * 72 + hs * 16 + a_k) * 2);
                ldm_x4(kh4, sKhiB + off);
                ldm_x4(kl4, sKloB + off);
                uint32_t bh0[2] = {kh4[0], kh4[2]}, bh1[2] = {kh4[1], kh4[3]};
                uint32_t bl0[2] = {kl4[0], kl4[2]}, bl1[2] = {kl4[1], kl4[3]};
                const int t0 = 2 * g16, t1 = t0 + 1;
                mma_f16(s[t0], qh[hs], bh0);
                mma_f16(s[t1], qh[hs], bh1);
                mma_f16(s[t0], qh[hs], bl0);
                mma_f16(s[t1], qh[hs], bl1);
            }
        }
        __syncthreads();     // all warps done reading K buffer
        if (kt + 1 < nkt) issue_K(kt + 1);
        cp_commit();         // group: K_{kt+1}

        // ---- causal mask (diagonal chunk only)
        if (kt == qt) {
            const int k0 = kt * 64;
            #pragma unroll
            for (int nt = 0; nt < 8; nt++) {
                const int kgb = k0 + nt * 8 + 2 * cq;
                if (kgb     > qg0) s[nt][0] = -1e30f;
                if (kgb + 1 > qg0) s[nt][1] = -1e30f;
                if (kgb     > qg1) s[nt][2] = -1e30f;
                if (kgb + 1 > qg1) s[nt][3] = -1e30f;
            }
        }

        // ---- online softmax
        float mx0 = mi0, mx1 = mi1;
        #pragma unroll
        for (int nt = 0; nt < 8; nt++) {
            mx0 = fmaxf(mx0, fmaxf(s[nt][0], s[nt][1]));
            mx1 = fmaxf(mx1, fmaxf(s[nt][2], s[nt][3]));
        }
        #pragma unroll
        for (int off = 1; off <= 2; off <<= 1) {
            mx0 = fmaxf(mx0, __shfl_xor_sync(0xffffffffu, mx0, off));
            mx1 = fmaxf(mx1, __shfl_xor_sync(0xffffffffu, mx1, off));
        }
        const float alpha0 = fex2((mi0 - mx0) * cE);
        const float alpha1 = fex2((mi1 - mx1) * cE);
        mi0 = mx0; mi1 = mx1;
        const float b0 = mx0 * cE, b1 = mx1 * cE;

        uint32_t ph[8][2];
        #pragma unroll
        for (int nt = 0; nt < 8; nt++) {
            float e0 = exp2_fast(fmaf(s[nt][0], cE, -b0));
            float e1 = exp2_fast(fmaf(s[nt][1], cE, -b0));
            float e2 = exp2_fast(fmaf(s[nt][2], cE, -b1));
            float e3 = exp2_fast(fmaf(s[nt][3], cE, -b1));
            ph[nt][0] = cvt_f16x2(e1, e0);
            ph[nt][1] = cvt_f16x2(e3, e2);
        }
        #pragma unroll
        for (int t = 0; t < 9; t++) {
            o[t][0] *= alpha0; o[t][1] *= alpha0;
            o[t][2] *= alpha1; o[t][3] *= alpha1;
        }

        cp_wait<1>();        // V_kt ready (K_{kt+1} in flight)
        __syncthreads();

        // ---- O += P @ V  (f16 2-term) + l via ones column, interleaved
        #pragma unroll
        for (int kb = 0; kb < 4; kb++) {
            uint32_t ap[4] = { ph[2 * kb][0], ph[2 * kb][1],
                               ph[2 * kb + 1][0], ph[2 * kb + 1][1] };
            #pragma unroll
            for (int ng = 0; ng < 4; ng++) {
                uint32_t vh4[4], vl4[4];
                uint32_t off = (uint32_t)(((kb * 16 + vb_k) * 88 + ng * 16 + vb_n) * 2);
                ldm_x4_t(vh4, sVhiB + off);
                ldm_x4_t(vl4, sVloB + off);
                uint32_t vh0[2] = {vh4[0], vh4[1]}, vh1[2] = {vh4[2], vh4[3]};
                uint32_t vl0[2] = {vl4[0], vl4[1]}, vl1[2] = {vl4[2], vl4[3]};
                mma_f16(o[2 * ng],     ap, vh0);
                mma_f16(o[2 * ng + 1], ap, vh1);
                mma_f16(o[2 * ng],     ap, vl0);
                mma_f16(o[2 * ng + 1], ap, vl1);
            }
            uint32_t vo[2];
            uint32_t off1 = (uint32_t)(((kb * 16 + vb_k) * 88 + 64) * 2);
            ldm_x2_t(vo, sVhiB + off1);
            mma_f16(o[8], ap, vo);
        }
        __syncthreads();     // all warps done reading V buffer
        if (kt + 1 < nkt) issue_V(kt + 1);
        cp_commit();         // group: V_{kt+1}
    }

    // ---- epilogue: normalize by l, emit f16 (single stream)
    const float l0 = __shfl_sync(0xffffffffu, o[8][0], lane & 28);
    const float l1 = __shfl_sync(0xffffffffu, o[8][2], lane & 28);
    const float i0 = 1.f / l0;
    const float i1 = 1.f / l1;
    const size_t r0 = (size_t)(b * T_ + q0 + wid * 16 + g);
    #pragma unroll
    for (int nt = 0; nt < 8; nt++) {
        const int cc = h * HD_ + nt * 8 + 2 * cq;
        *(uint32_t*)&oa[r0 * C_ + cc] =
            cvt_f16x2(o[nt][1] * i0, o[nt][0] * i0);
        *(uint32_t*)&oa[(r0 + 8) * C_ + cc] =
            cvt_f16x2(o[nt][3] * i1, o[nt][2] * i1);
    }
}

// ---------------------------------------------------------------------------
extern "C" void kernel_launch(void* const* d_in, const int* in_sizes, int n_in,
                              void* d_out, int out_size)
{
    const float* x     = (const float*)d_in[0];
    const float* Wqkv  = (const float*)d_in[1];
    const float* bqkv  = (const float*)d_in[2];
    const float* Wproj = (const float*)d_in[3];
    const float* bproj = (const float*)d_in[4];
    float* out = (float*)d_out;

    __half *xh, *wqh, *wql, *wph, *wpl, *oa;
    __half *fqh, *fql, *fkh, *fkl, *fvh, *fvl;
    cudaGetSymbolAddress((void**)&xh,  g_xh);
    cudaGetSymbolAddress((void**)&wqh, g_wqh);
    cudaGetSymbolAddress((void**)&wql, g_wql);
    cudaGetSymbolAddress((void**)&wph, g_wph);
    cudaGetSymbolAddress((void**)&wpl, g_wpl);
    cudaGetSymbolAddress((void**)&oa,  g_oa);
    cudaGetSymbolAddress((void**)&fqh, g_fqh);
    cudaGetSymbolAddress((void**)&fql, g_fql);
    cudaGetSymbolAddress((void**)&fkh, g_fkh);
    cudaGetSymbolAddress((void**)&fkl, g_fkl);
    cudaGetSymbolAddress((void**)&fvh, g_fvh);
    cudaGetSymbolAddress((void**)&fvl, g_fvl);

    cudaFuncSetAttribute(gemm_f16x2_kernel<1>,
                         cudaFuncAttributeMaxDynamicSharedMemorySize,
                         (int)G_SMEM_BYTES);
    cudaFuncSetAttribute(gemm_f16x2_kernel<0>,
                         cudaFuncAttributeMaxDynamicSharedMemorySize,
                         (int)G_SMEM_BYTES);

    // 0) merged split: x -> f16; Wqkv, Wproj -> f16 hi/lo (one launch)
    split_all_kernel<<<(N_TOT4 + 255) / 256, 256>>>(
        x, Wqkv, Wproj, xh, wqh, wql, wph, wpl);

    // 1) QKV GEMM (f16x2) with fused f16 q/k/v split epilogue
    gemm_f16x2_kernel<1><<<dim3(C3_ / 128, MR_ / 128), 256, G_SMEM_BYTES>>>(
        xh, wqh, wql, bqkv, nullptr,
        fqh, fql, fkh, fkl, fvh, fvl, MR_, C3_, C_);

    // 2) pipelined tensor-core flash attention -> f16 [4096, 768]
    attn_mma_kernel<<<dim3(T_ / 64, NH_, B_), 128>>>(
        fqh, fkh, fkl, fvh, fvl, oa);

    // 3) out = attn @ Wproj + bproj   [4096, 768]  (f16x2)
    gemm_f16x2_kernel<0><<<dim3(C_ / 128, MR_ / 128), 256, G_SMEM_BYTES>>>(
        oa, wph, wpl, bproj, out,
        nullptr, nullptr, nullptr, nullptr, nullptr, nullptr, MR_, C_, C_);
}